// round 1
// baseline (speedup 1.0000x reference)
#include <cuda_runtime.h>
#include <math.h>

static constexpr int N   = 100000;
static constexpr int E   = 1600000;
static constexpr int H   = 128;
static constexpr int OUTC = 64;
static constexpr int L   = 3;
static constexpr int G   = 3;
static constexpr int C   = 16;

// ---------------- device scratch (static globals; no runtime allocation) ----
__device__ int   g_cnt[N];
__device__ int   g_row[N];
__device__ int   g_cur[N];
__device__ int   g_bsum[128];
__device__ int   g_csr[E];
__device__ float g_hA[(size_t)N * H];
__device__ float g_hB[(size_t)N * H];
__device__ float g_z[(size_t)N * H];
__device__ float g_agg[(size_t)N * H];
__device__ float g_cbn[L * G * C * H];
__device__ float g_loss;

// ---------------- small utility kernels -------------------------------------
__global__ void k_zero(int* cnt, int* cur, float* loss) {
    int i = blockIdx.x * blockDim.x + threadIdx.x;
    if (i < N) { cnt[i] = 0; cur[i] = 0; }
    if (i == 0) *loss = 0.f;
}

__global__ void k_count(const int* __restrict__ ei, int* __restrict__ cnt) {
    int e = blockIdx.x * blockDim.x + threadIdx.x;
    if (e < E) atomicAdd(&cnt[ei[E + e]], 1);
}

__global__ void k_scan_block(const int* __restrict__ cnt, int* __restrict__ excl,
                             int* __restrict__ bsum) {
    __shared__ int s[1024];
    int i = blockIdx.x * 1024 + threadIdx.x;
    int v = (i < N) ? cnt[i] : 0;
    s[threadIdx.x] = v;
    __syncthreads();
    for (int off = 1; off < 1024; off <<= 1) {
        int t = (threadIdx.x >= off) ? s[threadIdx.x - off] : 0;
        __syncthreads();
        s[threadIdx.x] += t;
        __syncthreads();
    }
    if (i < N) excl[i] = s[threadIdx.x] - v;
    if (threadIdx.x == 1023) bsum[blockIdx.x] = s[1023];
}

__global__ void k_scan_sums(int* __restrict__ bsum, int nb) {
    __shared__ int s[128];
    int t = threadIdx.x;
    int v = (t < nb) ? bsum[t] : 0;
    s[t] = v;
    __syncthreads();
    for (int off = 1; off < 128; off <<= 1) {
        int u = (t >= off) ? s[t - off] : 0;
        __syncthreads();
        s[t] += u;
        __syncthreads();
    }
    if (t < nb) bsum[t] = s[t] - v;  // exclusive
}

__global__ void k_scan_add(int* __restrict__ excl, const int* __restrict__ bsum) {
    int i = blockIdx.x * 1024 + threadIdx.x;
    if (i < N) excl[i] += bsum[blockIdx.x];
}

__global__ void k_fill(const int* __restrict__ ei, const int* __restrict__ row,
                       int* __restrict__ cur, int* __restrict__ csr) {
    int e = blockIdx.x * blockDim.x + threadIdx.x;
    if (e < E) {
        int d = ei[E + e];
        int p = atomicAdd(&cur[d], 1);
        csr[row[d] + p] = ei[e];
    }
}

// normalize all codebook rows once: 144 rows of 128 floats, 1 warp per row
__global__ void k_cbnorm(const float* __restrict__ cb, float* __restrict__ cbn) {
    int id = blockIdx.x;
    int lane = threadIdx.x;
    float4 v = reinterpret_cast<const float4*>(cb + (size_t)id * 128)[lane];
    float sq = v.x * v.x + v.y * v.y + v.z * v.z + v.w * v.w;
    #pragma unroll
    for (int o = 16; o > 0; o >>= 1) sq += __shfl_xor_sync(0xffffffffu, sq, o);
    float inv = 1.f / (sqrtf(sq) + 1e-8f);
    v.x *= inv; v.y *= inv; v.z *= inv; v.w *= inv;
    reinterpret_cast<float4*>(cbn + (size_t)id * 128)[lane] = v;
}

// ---------------- LayerNorm + ReLU (one node per 128-thread block) ----------
__global__ void k_ln(const float* __restrict__ h, const float* __restrict__ g,
                     const float* __restrict__ b, float* __restrict__ z) {
    int n = blockIdx.x, t = threadIdx.x;
    float v = h[(size_t)n * 128 + t];
    float s = v, sq = v * v;
    #pragma unroll
    for (int o = 16; o > 0; o >>= 1) {
        s  += __shfl_xor_sync(0xffffffffu, s, o);
        sq += __shfl_xor_sync(0xffffffffu, sq, o);
    }
    __shared__ float s1[4], s2[4];
    int w = t >> 5;
    if ((t & 31) == 0) { s1[w] = s; s2[w] = sq; }
    __syncthreads();
    float S = s1[0] + s1[1] + s1[2] + s1[3];
    float Q = s2[0] + s2[1] + s2[2] + s2[3];
    float m = S * (1.f / 128.f);
    float var = Q * (1.f / 128.f) - m * m;
    float o = (v - m) * rsqrtf(var + 1e-5f) * g[t] + b[t];
    z[(size_t)n * 128 + t] = fmaxf(o, 0.f);
}

// ---------------- mean aggregation over CSR (one node per block) ------------
__global__ void k_agg(const float* __restrict__ z, const int* __restrict__ csr,
                      const int* __restrict__ row, const int* __restrict__ cnt,
                      float* __restrict__ agg) {
    int n = blockIdx.x, t = threadIdx.x;
    int start = row[n];
    int dg = cnt[n];
    float a0 = 0.f, a1 = 0.f, a2 = 0.f, a3 = 0.f;
    int i = 0;
    for (; i + 4 <= dg; i += 4) {
        int s0 = csr[start + i];
        int s1 = csr[start + i + 1];
        int s2 = csr[start + i + 2];
        int s3 = csr[start + i + 3];
        a0 += z[(size_t)s0 * 128 + t];
        a1 += z[(size_t)s1 * 128 + t];
        a2 += z[(size_t)s2 * 128 + t];
        a3 += z[(size_t)s3 * 128 + t];
    }
    for (; i < dg; i++) a0 += z[(size_t)csr[start + i] * 128 + t];
    float inv = dg > 0 ? 1.f / (float)dg : 0.f;
    agg[(size_t)n * 128 + t] = (a0 + a1 + a2 + a3) * inv;
}

// ---------------- GEMM: C[N,NCOL] = A1 @ W1^T + bias (+ A2 @ W2^T) ----------
// 32 rows/block, 256 threads (8 warps x 4 rows), full W in smem (k-major).
template <int NCOL, bool DUAL>
__launch_bounds__(256)
__global__ void k_gemm(const float* __restrict__ A1, const float* __restrict__ W1,
                       const float* __restrict__ bias,
                       const float* __restrict__ A2, const float* __restrict__ W2,
                       float* __restrict__ Cout) {
    constexpr int VEC  = NCOL / 32;
    constexpr int WSTR = NCOL + 4;  // pad to break smem store conflicts
    extern __shared__ float sm[];
    float* Ws1 = sm;                    // 128 * WSTR
    float* As1 = Ws1 + 128 * WSTR;      // 32 * 128
    float* Ws2 = As1 + 32 * 128;        // (DUAL) 128 * WSTR
    float* As2 = Ws2 + (DUAL ? 128 * WSTR : 0);

    const int tid  = threadIdx.x;
    const int row0 = blockIdx.x * 32;

    for (int idx = tid; idx < NCOL * 128; idx += 256) {
        int ncol = idx >> 7, k = idx & 127;
        Ws1[k * WSTR + ncol] = W1[idx];
    }
    for (int idx = tid; idx < 32 * 128; idx += 256)
        As1[idx] = A1[(size_t)row0 * 128 + idx];
    if (DUAL) {
        for (int idx = tid; idx < NCOL * 128; idx += 256) {
            int ncol = idx >> 7, k = idx & 127;
            Ws2[k * WSTR + ncol] = W2[idx];
        }
        for (int idx = tid; idx < 32 * 128; idx += 256)
            As2[idx] = A2[(size_t)row0 * 128 + idx];
    }
    __syncthreads();

    const int warp = tid >> 5, lane = tid & 31;
    float acc[4][VEC];
    #pragma unroll
    for (int r = 0; r < 4; r++)
        #pragma unroll
        for (int j = 0; j < VEC; j++) acc[r][j] = 0.f;

    const float* As = As1;
    const float* Ws = Ws1;
    #pragma unroll 1
    for (int pass = 0; pass < (DUAL ? 2 : 1); pass++) {
        if (pass == 1) { As = As2; Ws = Ws2; }
        for (int k4 = 0; k4 < 128; k4 += 4) {
            float4 a4[4];
            #pragma unroll
            for (int r = 0; r < 4; r++)
                a4[r] = *reinterpret_cast<const float4*>(&As[(warp * 4 + r) * 128 + k4]);
            #pragma unroll
            for (int kk = 0; kk < 4; kk++) {
                float wv[VEC];
                if constexpr (VEC == 4) {
                    float4 w = *reinterpret_cast<const float4*>(&Ws[(k4 + kk) * WSTR + lane * 4]);
                    wv[0] = w.x; wv[1] = w.y; wv[2] = w.z; wv[3] = w.w;
                } else {
                    float2 w = *reinterpret_cast<const float2*>(&Ws[(k4 + kk) * WSTR + lane * 2]);
                    wv[0] = w.x; wv[1] = w.y;
                }
                #pragma unroll
                for (int r = 0; r < 4; r++) {
                    float a = (kk == 0) ? a4[r].x : (kk == 1) ? a4[r].y
                              : (kk == 2) ? a4[r].z : a4[r].w;
                    #pragma unroll
                    for (int j = 0; j < VEC; j++)
                        acc[r][j] = fmaf(a, wv[j], acc[r][j]);
                }
            }
        }
    }

    float bv[VEC];
    #pragma unroll
    for (int j = 0; j < VEC; j++) bv[j] = bias[lane * VEC + j];
    #pragma unroll
    for (int r = 0; r < 4; r++) {
        int rowi = row0 + warp * 4 + r;
        #pragma unroll
        for (int j = 0; j < VEC; j++)
            Cout[(size_t)rowi * NCOL + lane * VEC + j] = acc[r][j] + bv[j];
    }
}

// ---------------- residual VQ: one node per warp, 3 stages fused ------------
__global__ void k_vq(const float* __restrict__ h, const float* __restrict__ cbn,
                     float* __restrict__ ids, int l, float* __restrict__ loss) {
    __shared__ float bl;
    if (threadIdx.x == 0) bl = 0.f;
    __syncthreads();
    int node = blockIdx.x * 8 + (threadIdx.x >> 5);
    int lane = threadIdx.x & 31;
    float4 r = reinterpret_cast<const float4*>(h + (size_t)node * 128)[lane];
    float lsum = 0.f;
    for (int q = 0; q < G; q++) {
        const float* cb = cbn + q * C * 128;
        float best = -1e30f;
        int bi = 0;
        #pragma unroll 4
        for (int c = 0; c < C; c++) {
            float4 w = reinterpret_cast<const float4*>(cb + (size_t)c * 128)[lane];
            float p = r.x * w.x + r.y * w.y + r.z * w.z + r.w * w.w;
            #pragma unroll
            for (int o = 16; o > 0; o >>= 1) p += __shfl_xor_sync(0xffffffffu, p, o);
            if (p > best) { best = p; bi = c; }  // '>' keeps first index (matches argmax)
        }
        float4 w = reinterpret_cast<const float4*>(cb + (size_t)bi * 128)[lane];
        r.x -= w.x; r.y -= w.y; r.z -= w.z; r.w -= w.w;
        lsum += r.x * r.x + r.y * r.y + r.z * r.z + r.w * r.w;
        if (lane == 0) ids[(size_t)node * (L * G) + l * G + q] = (float)bi;
    }
    #pragma unroll
    for (int o = 16; o > 0; o >>= 1) lsum += __shfl_xor_sync(0xffffffffu, lsum, o);
    if (lane == 0) atomicAdd(&bl, lsum);
    __syncthreads();
    if (threadIdx.x == 0) atomicAdd(loss, bl);
}

__global__ void k_fin(const float* __restrict__ loss, float* __restrict__ dst) {
    *dst = (*loss) * (0.25f / ((float)N * (float)H));
}

// ---------------- host orchestration ----------------------------------------
extern "C" void kernel_launch(void* const* d_in, const int* in_sizes, int n_in,
                              void* d_out, int out_size) {
    const float* x        = (const float*)d_in[0];
    const int*   ei       = (const int*)d_in[1];
    const float* lin1_w   = (const float*)d_in[2];
    const float* lin1_b   = (const float*)d_in[3];
    const float* norms_g  = (const float*)d_in[4];
    const float* norms_b  = (const float*)d_in[5];
    const float* convl_w  = (const float*)d_in[6];
    const float* convl_b  = (const float*)d_in[7];
    const float* convr_w  = (const float*)d_in[8];
    const float* codebooks= (const float*)d_in[9];
    const float* fnorm_g  = (const float*)d_in[10];
    const float* fnorm_b  = (const float*)d_in[11];
    const float* lin2_w   = (const float*)d_in[12];
    const float* lin2_b   = (const float*)d_in[13];
    float* out = (float*)d_out;

    int *cnt, *row, *cur, *bsum, *csr;
    float *hA, *hB, *z, *agg, *cbn, *loss;
    cudaGetSymbolAddress((void**)&cnt,  g_cnt);
    cudaGetSymbolAddress((void**)&row,  g_row);
    cudaGetSymbolAddress((void**)&cur,  g_cur);
    cudaGetSymbolAddress((void**)&bsum, g_bsum);
    cudaGetSymbolAddress((void**)&csr,  g_csr);
    cudaGetSymbolAddress((void**)&hA,   g_hA);
    cudaGetSymbolAddress((void**)&hB,   g_hB);
    cudaGetSymbolAddress((void**)&z,    g_z);
    cudaGetSymbolAddress((void**)&agg,  g_agg);
    cudaGetSymbolAddress((void**)&cbn,  g_cbn);
    cudaGetSymbolAddress((void**)&loss, g_loss);

    constexpr int SMEM_S = (128 * (128 + 4) + 32 * 128) * 4;           // 83968
    constexpr int SMEM_D = (2 * 128 * (128 + 4) + 2 * 32 * 128) * 4;   // 167936
    constexpr int SMEM_O = (128 * (64 + 4) + 32 * 128) * 4;            // 51200
    cudaFuncSetAttribute(k_gemm<128, false>, cudaFuncAttributeMaxDynamicSharedMemorySize, SMEM_S);
    cudaFuncSetAttribute(k_gemm<128, true>,  cudaFuncAttributeMaxDynamicSharedMemorySize, SMEM_D);
    cudaFuncSetAttribute(k_gemm<64, false>,  cudaFuncAttributeMaxDynamicSharedMemorySize, SMEM_O);

    const int NB = (N + 1023) / 1024;  // 98

    k_zero<<<(N + 255) / 256, 256>>>(cnt, cur, loss);
    k_count<<<(E + 255) / 256, 256>>>(ei, cnt);
    k_scan_block<<<NB, 1024>>>(cnt, row, bsum);
    k_scan_sums<<<1, 128>>>(bsum, NB);
    k_scan_add<<<NB, 1024>>>(row, bsum);
    k_fill<<<(E + 255) / 256, 256>>>(ei, row, cur, csr);
    k_cbnorm<<<L * G * C, 32>>>(codebooks, cbn);

    k_gemm<128, false><<<N / 32, 256, SMEM_S>>>(x, lin1_w, lin1_b, nullptr, nullptr, hA);

    float* hcur = hA;
    float* hnext = hB;
    for (int l = 0; l < L; l++) {
        k_ln<<<N, 128>>>(hcur, norms_g + (size_t)l * H, norms_b + (size_t)l * H, z);
        k_agg<<<N, 128>>>(z, csr, row, cnt, agg);
        k_gemm<128, true><<<N / 32, 256, SMEM_D>>>(
            agg, convl_w + (size_t)l * H * H, convl_b + (size_t)l * H,
            z,   convr_w + (size_t)l * H * H, hnext);
        k_vq<<<N / 8, 256>>>(hnext, cbn + (size_t)l * G * C * H,
                             out + (size_t)N * OUTC + 1, l, loss);
        float* t = hcur; hcur = hnext; hnext = t;
    }

    k_ln<<<N, 128>>>(hcur, fnorm_g, fnorm_b, z);
    k_gemm<64, false><<<N / 32, 256, SMEM_O>>>(z, lin2_w, lin2_b, nullptr, nullptr, out);
    k_fin<<<1, 1>>>(loss, out + (size_t)N * OUTC);
}

// round 4
// speedup vs baseline: 1.4140x; 1.4140x over previous
#include <cuda_runtime.h>
#include <math.h>

static constexpr int N   = 100000;
static constexpr int E   = 1600000;
static constexpr int H   = 128;
static constexpr int OUTC = 64;
static constexpr int L   = 3;
static constexpr int G   = 3;
static constexpr int C   = 16;

// ---------------- device scratch (static globals; no runtime allocation) ----
__device__ int   g_cnt[N];
__device__ int   g_row[N];
__device__ int   g_cur[N];
__device__ int   g_bsum[128];
__device__ int   g_csr[E];
__device__ float g_hA[(size_t)N * H];
__device__ float g_hB[(size_t)N * H];
__device__ float g_z[(size_t)N * H];
__device__ float g_agg[(size_t)N * H];
__device__ float g_cbn[L * G * C * H];
__device__ float g_loss;

// ---------------- small utility kernels -------------------------------------
__global__ void k_zero(int* cnt, int* cur, float* loss) {
    int i = blockIdx.x * blockDim.x + threadIdx.x;
    if (i < N) { cnt[i] = 0; cur[i] = 0; }
    if (i == 0) *loss = 0.f;
}

__global__ void k_count(const int* __restrict__ ei, int* __restrict__ cnt) {
    int e = blockIdx.x * blockDim.x + threadIdx.x;
    if (e < E) atomicAdd(&cnt[ei[E + e]], 1);
}

__global__ void k_scan_block(const int* __restrict__ cnt, int* __restrict__ excl,
                             int* __restrict__ bsum) {
    __shared__ int s[1024];
    int i = blockIdx.x * 1024 + threadIdx.x;
    int v = (i < N) ? cnt[i] : 0;
    s[threadIdx.x] = v;
    __syncthreads();
    for (int off = 1; off < 1024; off <<= 1) {
        int t = (threadIdx.x >= off) ? s[threadIdx.x - off] : 0;
        __syncthreads();
        s[threadIdx.x] += t;
        __syncthreads();
    }
    if (i < N) excl[i] = s[threadIdx.x] - v;
    if (threadIdx.x == 1023) bsum[blockIdx.x] = s[1023];
}

__global__ void k_scan_sums(int* __restrict__ bsum, int nb) {
    __shared__ int s[128];
    int t = threadIdx.x;
    int v = (t < nb) ? bsum[t] : 0;
    s[t] = v;
    __syncthreads();
    for (int off = 1; off < 128; off <<= 1) {
        int u = (t >= off) ? s[t - off] : 0;
        __syncthreads();
        s[t] += u;
        __syncthreads();
    }
    if (t < nb) bsum[t] = s[t] - v;  // exclusive
}

__global__ void k_scan_add(int* __restrict__ excl, const int* __restrict__ bsum) {
    int i = blockIdx.x * 1024 + threadIdx.x;
    if (i < N) excl[i] += bsum[blockIdx.x];
}

__global__ void k_fill(const int* __restrict__ ei, const int* __restrict__ row,
                       int* __restrict__ cur, int* __restrict__ csr) {
    int e = blockIdx.x * blockDim.x + threadIdx.x;
    if (e < E) {
        int d = ei[E + e];
        int p = atomicAdd(&cur[d], 1);
        csr[row[d] + p] = ei[e];
    }
}

// normalize all codebook rows once: 144 rows of 128 floats, 1 warp per row
__global__ void k_cbnorm(const float* __restrict__ cb, float* __restrict__ cbn) {
    int id = blockIdx.x;
    int lane = threadIdx.x;
    float4 v = reinterpret_cast<const float4*>(cb + (size_t)id * 128)[lane];
    float sq = v.x * v.x + v.y * v.y + v.z * v.z + v.w * v.w;
    #pragma unroll
    for (int o = 16; o > 0; o >>= 1) sq += __shfl_xor_sync(0xffffffffu, sq, o);
    float inv = 1.f / (sqrtf(sq) + 1e-8f);
    v.x *= inv; v.y *= inv; v.z *= inv; v.w *= inv;
    reinterpret_cast<float4*>(cbn + (size_t)id * 128)[lane] = v;
}

// ---------------- LayerNorm + ReLU (one node per 128-thread block) ----------
__global__ void k_ln(const float* __restrict__ h, const float* __restrict__ g,
                     const float* __restrict__ b, float* __restrict__ z) {
    int n = blockIdx.x, t = threadIdx.x;
    float v = h[(size_t)n * 128 + t];
    float s = v, sq = v * v;
    #pragma unroll
    for (int o = 16; o > 0; o >>= 1) {
        s  += __shfl_xor_sync(0xffffffffu, s, o);
        sq += __shfl_xor_sync(0xffffffffu, sq, o);
    }
    __shared__ float s1[4], s2[4];
    int w = t >> 5;
    if ((t & 31) == 0) { s1[w] = s; s2[w] = sq; }
    __syncthreads();
    float S = s1[0] + s1[1] + s1[2] + s1[3];
    float Q = s2[0] + s2[1] + s2[2] + s2[3];
    float m = S * (1.f / 128.f);
    float var = Q * (1.f / 128.f) - m * m;
    float o = (v - m) * rsqrtf(var + 1e-5f) * g[t] + b[t];
    z[(size_t)n * 128 + t] = fmaxf(o, 0.f);
}

// ---------------- mean aggregation over CSR (one node per block) ------------
__global__ void k_agg(const float* __restrict__ z, const int* __restrict__ csr,
                      const int* __restrict__ row, const int* __restrict__ cnt,
                      float* __restrict__ agg) {
    int n = blockIdx.x, t = threadIdx.x;
    int start = row[n];
    int dg = cnt[n];
    float a0 = 0.f, a1 = 0.f, a2 = 0.f, a3 = 0.f;
    int i = 0;
    for (; i + 4 <= dg; i += 4) {
        int s0 = csr[start + i];
        int s1 = csr[start + i + 1];
        int s2 = csr[start + i + 2];
        int s3 = csr[start + i + 3];
        a0 += z[(size_t)s0 * 128 + t];
        a1 += z[(size_t)s1 * 128 + t];
        a2 += z[(size_t)s2 * 128 + t];
        a3 += z[(size_t)s3 * 128 + t];
    }
    for (; i < dg; i++) a0 += z[(size_t)csr[start + i] * 128 + t];
    float inv = dg > 0 ? 1.f / (float)dg : 0.f;
    agg[(size_t)n * 128 + t] = (a0 + a1 + a2 + a3) * inv;
}

// ---------------- GEMM: C[N,NCOL] = A1 @ W1^T + bias (+ A2 @ W2^T) ----------
// 32 rows/block, 256 threads (8 warps x 4 rows), full W in smem (k-major).
template <int NCOL, bool DUAL>
__launch_bounds__(256)
__global__ void k_gemm(const float* __restrict__ A1, const float* __restrict__ W1,
                       const float* __restrict__ bias,
                       const float* __restrict__ A2, const float* __restrict__ W2,
                       float* __restrict__ Cout) {
    constexpr int VEC  = NCOL / 32;
    constexpr int WSTR = NCOL + 4;  // pad to break smem store conflicts
    extern __shared__ float sm[];
    float* Ws1 = sm;                    // 128 * WSTR
    float* As1 = Ws1 + 128 * WSTR;      // 32 * 128
    float* Ws2 = As1 + 32 * 128;        // (DUAL) 128 * WSTR
    float* As2 = Ws2 + (DUAL ? 128 * WSTR : 0);

    const int tid  = threadIdx.x;
    const int row0 = blockIdx.x * 32;

    for (int idx = tid; idx < NCOL * 128; idx += 256) {
        int ncol = idx >> 7, k = idx & 127;
        Ws1[k * WSTR + ncol] = W1[idx];
    }
    for (int idx = tid; idx < 32 * 128; idx += 256)
        As1[idx] = A1[(size_t)row0 * 128 + idx];
    if (DUAL) {
        for (int idx = tid; idx < NCOL * 128; idx += 256) {
            int ncol = idx >> 7, k = idx & 127;
            Ws2[k * WSTR + ncol] = W2[idx];
        }
        for (int idx = tid; idx < 32 * 128; idx += 256)
            As2[idx] = A2[(size_t)row0 * 128 + idx];
    }
    __syncthreads();

    const int warp = tid >> 5, lane = tid & 31;
    float acc[4][VEC];
    #pragma unroll
    for (int r = 0; r < 4; r++)
        #pragma unroll
        for (int j = 0; j < VEC; j++) acc[r][j] = 0.f;

    const float* As = As1;
    const float* Ws = Ws1;
    #pragma unroll 1
    for (int pass = 0; pass < (DUAL ? 2 : 1); pass++) {
        if (pass == 1) { As = As2; Ws = Ws2; }
        for (int k4 = 0; k4 < 128; k4 += 4) {
            float4 a4[4];
            #pragma unroll
            for (int r = 0; r < 4; r++)
                a4[r] = *reinterpret_cast<const float4*>(&As[(warp * 4 + r) * 128 + k4]);
            #pragma unroll
            for (int kk = 0; kk < 4; kk++) {
                float wv[VEC];
                if constexpr (VEC == 4) {
                    float4 w = *reinterpret_cast<const float4*>(&Ws[(k4 + kk) * WSTR + lane * 4]);
                    wv[0] = w.x; wv[1] = w.y; wv[2] = w.z; wv[3] = w.w;
                } else {
                    float2 w = *reinterpret_cast<const float2*>(&Ws[(k4 + kk) * WSTR + lane * 2]);
                    wv[0] = w.x; wv[1] = w.y;
                }
                #pragma unroll
                for (int r = 0; r < 4; r++) {
                    float a = (kk == 0) ? a4[r].x : (kk == 1) ? a4[r].y
                              : (kk == 2) ? a4[r].z : a4[r].w;
                    #pragma unroll
                    for (int j = 0; j < VEC; j++)
                        acc[r][j] = fmaf(a, wv[j], acc[r][j]);
                }
            }
        }
    }

    float bv[VEC];
    #pragma unroll
    for (int j = 0; j < VEC; j++) bv[j] = bias[lane * VEC + j];
    #pragma unroll
    for (int r = 0; r < 4; r++) {
        int rowi = row0 + warp * 4 + r;
        #pragma unroll
        for (int j = 0; j < VEC; j++)
            Cout[(size_t)rowi * NCOL + lane * VEC + j] = acc[r][j] + bv[j];
    }
}

// ---------------- residual VQ: one node per warp, 3 stages fused ------------
__global__ void k_vq(const float* __restrict__ h, const float* __restrict__ cbn,
                     float* __restrict__ ids, int l, float* __restrict__ loss) {
    __shared__ float bl;
    if (threadIdx.x == 0) bl = 0.f;
    __syncthreads();
    int node = blockIdx.x * 8 + (threadIdx.x >> 5);
    int lane = threadIdx.x & 31;
    float4 r = reinterpret_cast<const float4*>(h + (size_t)node * 128)[lane];
    float lsum = 0.f;
    for (int q = 0; q < G; q++) {
        const float* cb = cbn + q * C * 128;
        float best = -1e30f;
        int bi = 0;
        #pragma unroll 4
        for (int c = 0; c < C; c++) {
            float4 w = reinterpret_cast<const float4*>(cb + (size_t)c * 128)[lane];
            float p = r.x * w.x + r.y * w.y + r.z * w.z + r.w * w.w;
            #pragma unroll
            for (int o = 16; o > 0; o >>= 1) p += __shfl_xor_sync(0xffffffffu, p, o);
            if (p > best) { best = p; bi = c; }  // '>' keeps first index (matches argmax)
        }
        float4 w = reinterpret_cast<const float4*>(cb + (size_t)bi * 128)[lane];
        r.x -= w.x; r.y -= w.y; r.z -= w.z; r.w -= w.w;
        lsum += r.x * r.x + r.y * r.y + r.z * r.z + r.w * r.w;
        if (lane == 0) ids[(size_t)node * (L * G) + l * G + q] = (float)bi;
    }
    #pragma unroll
    for (int o = 16; o > 0; o >>= 1) lsum += __shfl_xor_sync(0xffffffffu, lsum, o);
    if (lane == 0) atomicAdd(&bl, lsum);
    __syncthreads();
    if (threadIdx.x == 0) atomicAdd(loss, bl);
}

__global__ void k_fin(const float* __restrict__ loss, float* __restrict__ dst) {
    *dst = (*loss) * (0.25f / ((float)N * (float)H));
}

// ---------------- host orchestration ----------------------------------------
extern "C" void kernel_launch(void* const* d_in, const int* in_sizes, int n_in,
                              void* d_out, int out_size) {
    const float* x        = (const float*)d_in[0];
    const int*   ei       = (const int*)d_in[1];
    const float* lin1_w   = (const float*)d_in[2];
    const float* lin1_b   = (const float*)d_in[3];
    const float* norms_g  = (const float*)d_in[4];
    const float* norms_b  = (const float*)d_in[5];
    const float* convl_w  = (const float*)d_in[6];
    const float* convl_b  = (const float*)d_in[7];
    const float* convr_w  = (const float*)d_in[8];
    const float* codebooks= (const float*)d_in[9];
    const float* fnorm_g  = (const float*)d_in[10];
    const float* fnorm_b  = (const float*)d_in[11];
    const float* lin2_w   = (const float*)d_in[12];
    const float* lin2_b   = (const float*)d_in[13];
    float* out = (float*)d_out;

    int *cnt, *row, *cur, *bsum, *csr;
    float *hA, *hB, *z, *agg, *cbn, *loss;
    cudaGetSymbolAddress((void**)&cnt,  g_cnt);
    cudaGetSymbolAddress((void**)&row,  g_row);
    cudaGetSymbolAddress((void**)&cur,  g_cur);
    cudaGetSymbolAddress((void**)&bsum, g_bsum);
    cudaGetSymbolAddress((void**)&csr,  g_csr);
    cudaGetSymbolAddress((void**)&hA,   g_hA);
    cudaGetSymbolAddress((void**)&hB,   g_hB);
    cudaGetSymbolAddress((void**)&z,    g_z);
    cudaGetSymbolAddress((void**)&agg,  g_agg);
    cudaGetSymbolAddress((void**)&cbn,  g_cbn);
    cudaGetSymbolAddress((void**)&loss, g_loss);

    constexpr int SMEM_S = (128 * (128 + 4) + 32 * 128) * 4;           // 83968
    constexpr int SMEM_D = (2 * 128 * (128 + 4) + 2 * 32 * 128) * 4;   // 167936
    constexpr int SMEM_O = (128 * (64 + 4) + 32 * 128) * 4;            // 51200
    cudaFuncSetAttribute(k_gemm<128, false>, cudaFuncAttributeMaxDynamicSharedMemorySize, SMEM_S);
    cudaFuncSetAttribute(k_gemm<128, true>,  cudaFuncAttributeMaxDynamicSharedMemorySize, SMEM_D);
    cudaFuncSetAttribute(k_gemm<64, false>,  cudaFuncAttributeMaxDynamicSharedMemorySize, SMEM_O);

    const int NB = (N + 1023) / 1024;  // 98

    k_zero<<<(N + 255) / 256, 256>>>(cnt, cur, loss);
    k_count<<<(E + 255) / 256, 256>>>(ei, cnt);
    k_scan_block<<<NB, 1024>>>(cnt, row, bsum);
    k_scan_sums<<<1, 128>>>(bsum, NB);
    k_scan_add<<<NB, 1024>>>(row, bsum);
    k_fill<<<(E + 255) / 256, 256>>>(ei, row, cur, csr);
    k_cbnorm<<<L * G * C, 32>>>(codebooks, cbn);

    k_gemm<128, false><<<N / 32, 256, SMEM_S>>>(x, lin1_w, lin1_b, nullptr, nullptr, hA);

    float* hcur = hA;
    float* hnext = hB;
    for (int l = 0; l < L; l++) {
        k_ln<<<N, 128>>>(hcur, norms_g + (size_t)l * H, norms_b + (size_t)l * H, z);
        k_agg<<<N, 128>>>(z, csr, row, cnt, agg);
        k_gemm<128, true><<<N / 32, 256, SMEM_D>>>(
            agg, convl_w + (size_t)l * H * H, convl_b + (size_t)l * H,
            z,   convr_w + (size_t)l * H * H, hnext);
        k_vq<<<N / 8, 256>>>(hnext, cbn + (size_t)l * G * C * H,
                             out + (size_t)N * OUTC + 1, l, loss);
        float* t = hcur; hcur = hnext; hnext = t;
    }

    k_ln<<<N, 128>>>(hcur, fnorm_g, fnorm_b, z);
    k_gemm<64, false><<<N / 32, 256, SMEM_O>>>(z, lin2_w, lin2_b, nullptr, nullptr, out);
    k_fin<<<1, 1>>>(loss, out + (size_t)N * OUTC);
}

// round 5
// speedup vs baseline: 1.4313x; 1.0123x over previous
#include <cuda_runtime.h>
#include <math.h>

static constexpr int N   = 100000;
static constexpr int E   = 1600000;
static constexpr int H   = 128;
static constexpr int OUTC = 64;
static constexpr int L   = 3;
static constexpr int G   = 3;
static constexpr int C   = 16;

// ---------------- device scratch (static globals; no runtime allocation) ----
__device__ int   g_cnt[N];
__device__ int   g_row[N];
__device__ int   g_cur[N];
__device__ int   g_bsum[128];
__device__ int   g_csr[E];
__device__ float g_hA[(size_t)N * H];
__device__ float g_hB[(size_t)N * H];
__device__ float g_z[(size_t)N * H];
__device__ float g_agg[(size_t)N * H];
__device__ float g_cbn[L * G * C * H];
__device__ float g_loss;

// ---------------- small utility kernels -------------------------------------
__global__ void k_zero(int* cnt, int* cur, float* loss) {
    int i = blockIdx.x * blockDim.x + threadIdx.x;
    if (i < N) { cnt[i] = 0; cur[i] = 0; }
    if (i == 0) *loss = 0.f;
}

__global__ void k_count(const int* __restrict__ ei, int* __restrict__ cnt) {
    int e = blockIdx.x * blockDim.x + threadIdx.x;
    if (e < E) atomicAdd(&cnt[ei[E + e]], 1);
}

__global__ void k_scan_block(const int* __restrict__ cnt, int* __restrict__ excl,
                             int* __restrict__ bsum) {
    __shared__ int s[1024];
    int i = blockIdx.x * 1024 + threadIdx.x;
    int v = (i < N) ? cnt[i] : 0;
    s[threadIdx.x] = v;
    __syncthreads();
    for (int off = 1; off < 1024; off <<= 1) {
        int t = (threadIdx.x >= off) ? s[threadIdx.x - off] : 0;
        __syncthreads();
        s[threadIdx.x] += t;
        __syncthreads();
    }
    if (i < N) excl[i] = s[threadIdx.x] - v;
    if (threadIdx.x == 1023) bsum[blockIdx.x] = s[1023];
}

__global__ void k_scan_sums(int* __restrict__ bsum, int nb) {
    __shared__ int s[128];
    int t = threadIdx.x;
    int v = (t < nb) ? bsum[t] : 0;
    s[t] = v;
    __syncthreads();
    for (int off = 1; off < 128; off <<= 1) {
        int u = (t >= off) ? s[t - off] : 0;
        __syncthreads();
        s[t] += u;
        __syncthreads();
    }
    if (t < nb) bsum[t] = s[t] - v;  // exclusive
}

__global__ void k_scan_add(int* __restrict__ excl, const int* __restrict__ bsum) {
    int i = blockIdx.x * 1024 + threadIdx.x;
    if (i < N) excl[i] += bsum[blockIdx.x];
}

__global__ void k_fill(const int* __restrict__ ei, const int* __restrict__ row,
                       int* __restrict__ cur, int* __restrict__ csr) {
    int e = blockIdx.x * blockDim.x + threadIdx.x;
    if (e < E) {
        int d = ei[E + e];
        int p = atomicAdd(&cur[d], 1);
        csr[row[d] + p] = ei[e];
    }
}

// normalize all codebook rows once: 144 rows of 128 floats, 1 warp per row
__global__ void k_cbnorm(const float* __restrict__ cb, float* __restrict__ cbn) {
    int id = blockIdx.x;
    int lane = threadIdx.x;
    float4 v = reinterpret_cast<const float4*>(cb + (size_t)id * 128)[lane];
    float sq = v.x * v.x + v.y * v.y + v.z * v.z + v.w * v.w;
    #pragma unroll
    for (int o = 16; o > 0; o >>= 1) sq += __shfl_xor_sync(0xffffffffu, sq, o);
    float inv = 1.f / (sqrtf(sq) + 1e-8f);
    v.x *= inv; v.y *= inv; v.z *= inv; v.w *= inv;
    reinterpret_cast<float4*>(cbn + (size_t)id * 128)[lane] = v;
}

// ---------------- LayerNorm + ReLU (one node per 128-thread block) ----------
__global__ void k_ln(const float* __restrict__ h, const float* __restrict__ g,
                     const float* __restrict__ b, float* __restrict__ z) {
    int n = blockIdx.x, t = threadIdx.x;
    float v = h[(size_t)n * 128 + t];
    float s = v, sq = v * v;
    #pragma unroll
    for (int o = 16; o > 0; o >>= 1) {
        s  += __shfl_xor_sync(0xffffffffu, s, o);
        sq += __shfl_xor_sync(0xffffffffu, sq, o);
    }
    __shared__ float s1[4], s2[4];
    int w = t >> 5;
    if ((t & 31) == 0) { s1[w] = s; s2[w] = sq; }
    __syncthreads();
    float S = s1[0] + s1[1] + s1[2] + s1[3];
    float Q = s2[0] + s2[1] + s2[2] + s2[3];
    float m = S * (1.f / 128.f);
    float var = Q * (1.f / 128.f) - m * m;
    float o = (v - m) * rsqrtf(var + 1e-5f) * g[t] + b[t];
    z[(size_t)n * 128 + t] = fmaxf(o, 0.f);
}

// ---------------- mean aggregation over CSR (one node per block) ------------
__global__ void k_agg(const float* __restrict__ z, const int* __restrict__ csr,
                      const int* __restrict__ row, const int* __restrict__ cnt,
                      float* __restrict__ agg) {
    int n = blockIdx.x, t = threadIdx.x;
    int start = row[n];
    int dg = cnt[n];
    float a0 = 0.f, a1 = 0.f, a2 = 0.f, a3 = 0.f;
    int i = 0;
    for (; i + 4 <= dg; i += 4) {
        int s0 = csr[start + i];
        int s1 = csr[start + i + 1];
        int s2 = csr[start + i + 2];
        int s3 = csr[start + i + 3];
        a0 += z[(size_t)s0 * 128 + t];
        a1 += z[(size_t)s1 * 128 + t];
        a2 += z[(size_t)s2 * 128 + t];
        a3 += z[(size_t)s3 * 128 + t];
    }
    for (; i < dg; i++) a0 += z[(size_t)csr[start + i] * 128 + t];
    float inv = dg > 0 ? 1.f / (float)dg : 0.f;
    agg[(size_t)n * 128 + t] = (a0 + a1 + a2 + a3) * inv;
}

// ---------------- GEMM: C[N,NCOL] = A1 @ W1^T + bias (+ A2 @ W2^T) ----------
// 32 rows/block, 256 threads (8 warps x 4 rows), full W in smem (k-major).
template <int NCOL, bool DUAL>
__launch_bounds__(256)
__global__ void k_gemm(const float* __restrict__ A1, const float* __restrict__ W1,
                       const float* __restrict__ bias,
                       const float* __restrict__ A2, const float* __restrict__ W2,
                       float* __restrict__ Cout) {
    constexpr int VEC  = NCOL / 32;
    constexpr int WSTR = NCOL + 4;  // pad to break smem store conflicts
    extern __shared__ float sm[];
    float* Ws1 = sm;                    // 128 * WSTR
    float* As1 = Ws1 + 128 * WSTR;      // 32 * 128
    float* Ws2 = As1 + 32 * 128;        // (DUAL) 128 * WSTR
    float* As2 = Ws2 + (DUAL ? 128 * WSTR : 0);

    const int tid  = threadIdx.x;
    const int row0 = blockIdx.x * 32;

    for (int idx = tid; idx < NCOL * 128; idx += 256) {
        int ncol = idx >> 7, k = idx & 127;
        Ws1[k * WSTR + ncol] = W1[idx];
    }
    for (int idx = tid; idx < 32 * 128; idx += 256)
        As1[idx] = A1[(size_t)row0 * 128 + idx];
    if (DUAL) {
        for (int idx = tid; idx < NCOL * 128; idx += 256) {
            int ncol = idx >> 7, k = idx & 127;
            Ws2[k * WSTR + ncol] = W2[idx];
        }
        for (int idx = tid; idx < 32 * 128; idx += 256)
            As2[idx] = A2[(size_t)row0 * 128 + idx];
    }
    __syncthreads();

    const int warp = tid >> 5, lane = tid & 31;
    float acc[4][VEC];
    #pragma unroll
    for (int r = 0; r < 4; r++)
        #pragma unroll
        for (int j = 0; j < VEC; j++) acc[r][j] = 0.f;

    const float* As = As1;
    const float* Ws = Ws1;
    #pragma unroll 1
    for (int pass = 0; pass < (DUAL ? 2 : 1); pass++) {
        if (pass == 1) { As = As2; Ws = Ws2; }
        for (int k4 = 0; k4 < 128; k4 += 4) {
            float4 a4[4];
            #pragma unroll
            for (int r = 0; r < 4; r++)
                a4[r] = *reinterpret_cast<const float4*>(&As[(warp * 4 + r) * 128 + k4]);
            #pragma unroll
            for (int kk = 0; kk < 4; kk++) {
                float wv[VEC];
                if constexpr (VEC == 4) {
                    float4 w = *reinterpret_cast<const float4*>(&Ws[(k4 + kk) * WSTR + lane * 4]);
                    wv[0] = w.x; wv[1] = w.y; wv[2] = w.z; wv[3] = w.w;
                } else {
                    float2 w = *reinterpret_cast<const float2*>(&Ws[(k4 + kk) * WSTR + lane * 2]);
                    wv[0] = w.x; wv[1] = w.y;
                }
                #pragma unroll
                for (int r = 0; r < 4; r++) {
                    float a = (kk == 0) ? a4[r].x : (kk == 1) ? a4[r].y
                              : (kk == 2) ? a4[r].z : a4[r].w;
                    #pragma unroll
                    for (int j = 0; j < VEC; j++)
                        acc[r][j] = fmaf(a, wv[j], acc[r][j]);
                }
            }
        }
    }

    float bv[VEC];
    #pragma unroll
    for (int j = 0; j < VEC; j++) bv[j] = bias[lane * VEC + j];
    #pragma unroll
    for (int r = 0; r < 4; r++) {
        int rowi = row0 + warp * 4 + r;
        #pragma unroll
        for (int j = 0; j < VEC; j++)
            Cout[(size_t)rowi * NCOL + lane * VEC + j] = acc[r][j] + bv[j];
    }
}

// ---------------- residual VQ: one node per warp, 3 stages fused ------------
__global__ void k_vq(const float* __restrict__ h, const float* __restrict__ cbn,
                     float* __restrict__ ids, int l, float* __restrict__ loss) {
    __shared__ float bl;
    if (threadIdx.x == 0) bl = 0.f;
    __syncthreads();
    int node = blockIdx.x * 8 + (threadIdx.x >> 5);
    int lane = threadIdx.x & 31;
    float4 r = reinterpret_cast<const float4*>(h + (size_t)node * 128)[lane];
    float lsum = 0.f;
    for (int q = 0; q < G; q++) {
        const float* cb = cbn + q * C * 128;
        float best = -1e30f;
        int bi = 0;
        #pragma unroll 4
        for (int c = 0; c < C; c++) {
            float4 w = reinterpret_cast<const float4*>(cb + (size_t)c * 128)[lane];
            float p = r.x * w.x + r.y * w.y + r.z * w.z + r.w * w.w;
            #pragma unroll
            for (int o = 16; o > 0; o >>= 1) p += __shfl_xor_sync(0xffffffffu, p, o);
            if (p > best) { best = p; bi = c; }  // '>' keeps first index (matches argmax)
        }
        float4 w = reinterpret_cast<const float4*>(cb + (size_t)bi * 128)[lane];
        r.x -= w.x; r.y -= w.y; r.z -= w.z; r.w -= w.w;
        lsum += r.x * r.x + r.y * r.y + r.z * r.z + r.w * r.w;
        if (lane == 0) ids[(size_t)node * (L * G) + l * G + q] = (float)bi;
    }
    #pragma unroll
    for (int o = 16; o > 0; o >>= 1) lsum += __shfl_xor_sync(0xffffffffu, lsum, o);
    if (lane == 0) atomicAdd(&bl, lsum);
    __syncthreads();
    if (threadIdx.x == 0) atomicAdd(loss, bl);
}

__global__ void k_fin(const float* __restrict__ loss, float* __restrict__ dst) {
    *dst = (*loss) * (0.25f / ((float)N * (float)H));
}

// ---------------- host orchestration ----------------------------------------
extern "C" void kernel_launch(void* const* d_in, const int* in_sizes, int n_in,
                              void* d_out, int out_size) {
    const float* x        = (const float*)d_in[0];
    const int*   ei       = (const int*)d_in[1];
    const float* lin1_w   = (const float*)d_in[2];
    const float* lin1_b   = (const float*)d_in[3];
    const float* norms_g  = (const float*)d_in[4];
    const float* norms_b  = (const float*)d_in[5];
    const float* convl_w  = (const float*)d_in[6];
    const float* convl_b  = (const float*)d_in[7];
    const float* convr_w  = (const float*)d_in[8];
    const float* codebooks= (const float*)d_in[9];
    const float* fnorm_g  = (const float*)d_in[10];
    const float* fnorm_b  = (const float*)d_in[11];
    const float* lin2_w   = (const float*)d_in[12];
    const float* lin2_b   = (const float*)d_in[13];
    float* out = (float*)d_out;

    int *cnt, *row, *cur, *bsum, *csr;
    float *hA, *hB, *z, *agg, *cbn, *loss;
    cudaGetSymbolAddress((void**)&cnt,  g_cnt);
    cudaGetSymbolAddress((void**)&row,  g_row);
    cudaGetSymbolAddress((void**)&cur,  g_cur);
    cudaGetSymbolAddress((void**)&bsum, g_bsum);
    cudaGetSymbolAddress((void**)&csr,  g_csr);
    cudaGetSymbolAddress((void**)&hA,   g_hA);
    cudaGetSymbolAddress((void**)&hB,   g_hB);
    cudaGetSymbolAddress((void**)&z,    g_z);
    cudaGetSymbolAddress((void**)&agg,  g_agg);
    cudaGetSymbolAddress((void**)&cbn,  g_cbn);
    cudaGetSymbolAddress((void**)&loss, g_loss);

    constexpr int SMEM_S = (128 * (128 + 4) + 32 * 128) * 4;           // 83968
    constexpr int SMEM_D = (2 * 128 * (128 + 4) + 2 * 32 * 128) * 4;   // 167936
    constexpr int SMEM_O = (128 * (64 + 4) + 32 * 128) * 4;            // 51200
    cudaFuncSetAttribute(k_gemm<128, false>, cudaFuncAttributeMaxDynamicSharedMemorySize, SMEM_S);
    cudaFuncSetAttribute(k_gemm<128, true>,  cudaFuncAttributeMaxDynamicSharedMemorySize, SMEM_D);
    cudaFuncSetAttribute(k_gemm<64, false>,  cudaFuncAttributeMaxDynamicSharedMemorySize, SMEM_O);

    const int NB = (N + 1023) / 1024;  // 98

    k_zero<<<(N + 255) / 256, 256>>>(cnt, cur, loss);
    k_count<<<(E + 255) / 256, 256>>>(ei, cnt);
    k_scan_block<<<NB, 1024>>>(cnt, row, bsum);
    k_scan_sums<<<1, 128>>>(bsum, NB);
    k_scan_add<<<NB, 1024>>>(row, bsum);
    k_fill<<<(E + 255) / 256, 256>>>(ei, row, cur, csr);
    k_cbnorm<<<L * G * C, 32>>>(codebooks, cbn);

    k_gemm<128, false><<<N / 32, 256, SMEM_S>>>(x, lin1_w, lin1_b, nullptr, nullptr, hA);

    float* hcur = hA;
    float* hnext = hB;
    for (int l = 0; l < L; l++) {
        k_ln<<<N, 128>>>(hcur, norms_g + (size_t)l * H, norms_b + (size_t)l * H, z);
        k_agg<<<N, 128>>>(z, csr, row, cnt, agg);
        k_gemm<128, true><<<N / 32, 256, SMEM_D>>>(
            agg, convl_w + (size_t)l * H * H, convl_b + (size_t)l * H,
            z,   convr_w + (size_t)l * H * H, hnext);
        k_vq<<<N / 8, 256>>>(hnext, cbn + (size_t)l * G * C * H,
                             out + (size_t)N * OUTC + 1, l, loss);
        float* t = hcur; hcur = hnext; hnext = t;
    }

    k_ln<<<N, 128>>>(hcur, fnorm_g, fnorm_b, z);
    k_gemm<64, false><<<N / 32, 256, SMEM_O>>>(z, lin2_w, lin2_b, nullptr, nullptr, out);
    k_fin<<<1, 1>>>(loss, out + (size_t)N * OUTC);
}

// round 6
// speedup vs baseline: 2.4952x; 1.7433x over previous
#include <cuda_runtime.h>
#include <math.h>

static constexpr int N   = 100000;
static constexpr int E   = 1600000;
static constexpr int H   = 128;
static constexpr int OUTC = 64;
static constexpr int L   = 3;
static constexpr int G   = 3;
static constexpr int C   = 16;

// ---------------- device scratch (static globals; no runtime allocation) ----
__device__ int   g_cnt[N];
__device__ int   g_row[N];
__device__ int   g_cur[N];
__device__ int   g_bsum[128];
__device__ int   g_csr[E];
__device__ float g_hA[(size_t)N * H];
__device__ float g_hB[(size_t)N * H];
__device__ float g_z[(size_t)N * H];
__device__ float g_agg[(size_t)N * H];
__device__ float g_cbn[L * G * C * H];
__device__ float g_loss;

// ---------------- packed f32x2 helpers ---------------------------------------
__device__ __forceinline__ unsigned long long fma2(unsigned long long a,
                                                   unsigned long long b,
                                                   unsigned long long c) {
    unsigned long long d;
    asm("fma.rn.f32x2 %0, %1, %2, %3;" : "=l"(d) : "l"(a), "l"(b), "l"(c));
    return d;
}
__device__ __forceinline__ unsigned long long packdup(float v) {
    unsigned long long p;
    asm("mov.b64 %0, {%1, %1};" : "=l"(p) : "f"(v));
    return p;
}

// ---------------- small utility kernels -------------------------------------
__global__ void k_zero(int* cnt, int* cur, float* loss) {
    int i = blockIdx.x * blockDim.x + threadIdx.x;
    if (i < N) { cnt[i] = 0; cur[i] = 0; }
    if (i == 0) *loss = 0.f;
}

__global__ void k_count(const int* __restrict__ ei, int* __restrict__ cnt) {
    int e = blockIdx.x * blockDim.x + threadIdx.x;
    if (e < E) atomicAdd(&cnt[ei[E + e]], 1);
}

__global__ void k_scan_block(const int* __restrict__ cnt, int* __restrict__ excl,
                             int* __restrict__ bsum) {
    __shared__ int s[1024];
    int i = blockIdx.x * 1024 + threadIdx.x;
    int v = (i < N) ? cnt[i] : 0;
    s[threadIdx.x] = v;
    __syncthreads();
    for (int off = 1; off < 1024; off <<= 1) {
        int t = (threadIdx.x >= off) ? s[threadIdx.x - off] : 0;
        __syncthreads();
        s[threadIdx.x] += t;
        __syncthreads();
    }
    if (i < N) excl[i] = s[threadIdx.x] - v;
    if (threadIdx.x == 1023) bsum[blockIdx.x] = s[1023];
}

__global__ void k_scan_sums(int* __restrict__ bsum, int nb) {
    __shared__ int s[128];
    int t = threadIdx.x;
    int v = (t < nb) ? bsum[t] : 0;
    s[t] = v;
    __syncthreads();
    for (int off = 1; off < 128; off <<= 1) {
        int u = (t >= off) ? s[t - off] : 0;
        __syncthreads();
        s[t] += u;
        __syncthreads();
    }
    if (t < nb) bsum[t] = s[t] - v;  // exclusive
}

__global__ void k_scan_add(int* __restrict__ excl, const int* __restrict__ bsum) {
    int i = blockIdx.x * 1024 + threadIdx.x;
    if (i < N) excl[i] += bsum[blockIdx.x];
}

__global__ void k_fill(const int* __restrict__ ei, const int* __restrict__ row,
                       int* __restrict__ cur, int* __restrict__ csr) {
    int e = blockIdx.x * blockDim.x + threadIdx.x;
    if (e < E) {
        int d = ei[E + e];
        int p = atomicAdd(&cur[d], 1);
        csr[row[d] + p] = ei[e];
    }
}

// normalize all codebook rows once: 144 rows of 128 floats, 1 warp per row
__global__ void k_cbnorm(const float* __restrict__ cb, float* __restrict__ cbn) {
    int id = blockIdx.x;
    int lane = threadIdx.x;
    float4 v = reinterpret_cast<const float4*>(cb + (size_t)id * 128)[lane];
    float sq = v.x * v.x + v.y * v.y + v.z * v.z + v.w * v.w;
    #pragma unroll
    for (int o = 16; o > 0; o >>= 1) sq += __shfl_xor_sync(0xffffffffu, sq, o);
    float inv = 1.f / (sqrtf(sq) + 1e-8f);
    v.x *= inv; v.y *= inv; v.z *= inv; v.w *= inv;
    reinterpret_cast<float4*>(cbn + (size_t)id * 128)[lane] = v;
}

// ---------------- LayerNorm + ReLU (one node per 128-thread block) ----------
__global__ void k_ln(const float* __restrict__ h, const float* __restrict__ g,
                     const float* __restrict__ b, float* __restrict__ z) {
    int n = blockIdx.x, t = threadIdx.x;
    float v = h[(size_t)n * 128 + t];
    float s = v, sq = v * v;
    #pragma unroll
    for (int o = 16; o > 0; o >>= 1) {
        s  += __shfl_xor_sync(0xffffffffu, s, o);
        sq += __shfl_xor_sync(0xffffffffu, sq, o);
    }
    __shared__ float s1[4], s2[4];
    int w = t >> 5;
    if ((t & 31) == 0) { s1[w] = s; s2[w] = sq; }
    __syncthreads();
    float S = s1[0] + s1[1] + s1[2] + s1[3];
    float Q = s2[0] + s2[1] + s2[2] + s2[3];
    float m = S * (1.f / 128.f);
    float var = Q * (1.f / 128.f) - m * m;
    float o = (v - m) * rsqrtf(var + 1e-5f) * g[t] + b[t];
    z[(size_t)n * 128 + t] = fmaxf(o, 0.f);
}

// ---------------- mean aggregation over CSR (one node per block) ------------
__global__ void k_agg(const float* __restrict__ z, const int* __restrict__ csr,
                      const int* __restrict__ row, const int* __restrict__ cnt,
                      float* __restrict__ agg) {
    int n = blockIdx.x, t = threadIdx.x;
    int start = row[n];
    int dg = cnt[n];
    float a0 = 0.f, a1 = 0.f, a2 = 0.f, a3 = 0.f;
    int i = 0;
    for (; i + 4 <= dg; i += 4) {
        int s0 = csr[start + i];
        int s1 = csr[start + i + 1];
        int s2 = csr[start + i + 2];
        int s3 = csr[start + i + 3];
        a0 += z[(size_t)s0 * 128 + t];
        a1 += z[(size_t)s1 * 128 + t];
        a2 += z[(size_t)s2 * 128 + t];
        a3 += z[(size_t)s3 * 128 + t];
    }
    for (; i < dg; i++) a0 += z[(size_t)csr[start + i] * 128 + t];
    float inv = dg > 0 ? 1.f / (float)dg : 0.f;
    agg[(size_t)n * 128 + t] = (a0 + a1 + a2 + a3) * inv;
}

// ---------------- FFMA2 GEMM: C[N,BN] = A1 @ W1^T + bias (+ A2 @ W2^T) ------
// BM=128 rows/block, BK=32 k-chunk, 256 threads.
// Thread (tx = tid%16, ty = tid/16): rows ty*8..+7, col-pairs {2tx+32c}.
// A stored in smem pre-packed as f32x2 duplicates (broadcast operand);
// W stored k-major so each lane reads a contiguous 8B pair -> conflict-free.
template <int BN, bool DUAL>
__global__ __launch_bounds__(256, 2)
void k_gemm2(const float* __restrict__ A1, const float* __restrict__ W1,
             const float* __restrict__ bias,
             const float* __restrict__ A2, const float* __restrict__ W2,
             float* __restrict__ Cout) {
    constexpr int BM = 128, BK = 32;
    constexpr int NP2 = BN / 32;       // col-pairs per thread (4 or 2)
    constexpr int ASTR = BK + 2;       // ull stride (even -> 16B-aligned ull2)
    constexpr int WSTR = BN + 4;       // float stride (even -> 8B-aligned ull)

    extern __shared__ char smraw[];
    unsigned long long* As = reinterpret_cast<unsigned long long*>(smraw); // [BM][ASTR]
    float* Ws = reinterpret_cast<float*>(As + BM * ASTR);                  // [BK][WSTR]

    const int tid = threadIdx.x;
    const int tx = tid & 15, ty = tid >> 4;
    const int row0 = blockIdx.x * BM;

    unsigned long long acc[8][NP2];
    #pragma unroll
    for (int r = 0; r < 8; r++)
        #pragma unroll
        for (int c = 0; c < NP2; c++) acc[r][c] = 0ull;

    #pragma unroll 1
    for (int pass = 0; pass < (DUAL ? 2 : 1); pass++) {
        const float* A = pass ? A2 : A1;
        const float* W = pass ? W2 : W1;
        #pragma unroll 1
        for (int kc = 0; kc < 128; kc += BK) {
            __syncthreads();
            // ---- load A chunk: BM x BK floats (1024 float4 units) ----
            #pragma unroll
            for (int i = 0; i < 4; i++) {
                int idx = tid + i * 256;
                int r = idx >> 3;
                int k4 = (idx & 7) * 4;
                int gr = row0 + r;
                float4 v = make_float4(0.f, 0.f, 0.f, 0.f);
                if (gr < N)
                    v = *reinterpret_cast<const float4*>(&A[(size_t)gr * 128 + kc + k4]);
                unsigned long long* dst = &As[r * ASTR + k4];
                dst[0] = packdup(v.x); dst[1] = packdup(v.y);
                dst[2] = packdup(v.z); dst[3] = packdup(v.w);
            }
            // ---- load W chunk: BN x BK floats, transposed to [k][n] ----
            #pragma unroll
            for (int i = 0; i < BN / 32; i++) {
                int idx = tid + i * 256;
                int n = idx >> 3;
                int k4 = (idx & 7) * 4;
                float4 w = *reinterpret_cast<const float4*>(&W[(size_t)n * 128 + kc + k4]);
                Ws[(k4 + 0) * WSTR + n] = w.x;
                Ws[(k4 + 1) * WSTR + n] = w.y;
                Ws[(k4 + 2) * WSTR + n] = w.z;
                Ws[(k4 + 3) * WSTR + n] = w.w;
            }
            __syncthreads();
            // ---- compute ----
            #pragma unroll
            for (int k = 0; k < BK; k += 2) {
                longlong2 ap[8];
                #pragma unroll
                for (int r = 0; r < 8; r++)
                    ap[r] = *reinterpret_cast<const longlong2*>(&As[(ty * 8 + r) * ASTR + k]);
                unsigned long long wp0[NP2], wp1[NP2];
                const unsigned long long* wr0 =
                    reinterpret_cast<const unsigned long long*>(Ws + k * WSTR);
                const unsigned long long* wr1 =
                    reinterpret_cast<const unsigned long long*>(Ws + (k + 1) * WSTR);
                #pragma unroll
                for (int c = 0; c < NP2; c++) {
                    wp0[c] = wr0[tx + 16 * c];
                    wp1[c] = wr1[tx + 16 * c];
                }
                #pragma unroll
                for (int r = 0; r < 8; r++)
                    #pragma unroll
                    for (int c = 0; c < NP2; c++) {
                        acc[r][c] = fma2((unsigned long long)ap[r].x, wp0[c], acc[r][c]);
                        acc[r][c] = fma2((unsigned long long)ap[r].y, wp1[c], acc[r][c]);
                    }
            }
        }
    }

    // ---- epilogue: add bias, store float2 pairs ----
    float2 bv[NP2];
    #pragma unroll
    for (int c = 0; c < NP2; c++) {
        int col = 2 * tx + 32 * c;
        bv[c].x = bias[col];
        bv[c].y = bias[col + 1];
    }
    #pragma unroll
    for (int r = 0; r < 8; r++) {
        int gr = row0 + ty * 8 + r;
        if (gr < N) {
            #pragma unroll
            for (int c = 0; c < NP2; c++) {
                float lo, hi;
                asm("mov.b64 {%0, %1}, %2;" : "=f"(lo), "=f"(hi) : "l"(acc[r][c]));
                float2 v = make_float2(lo + bv[c].x, hi + bv[c].y);
                *reinterpret_cast<float2*>(&Cout[(size_t)gr * BN + 2 * tx + 32 * c]) = v;
            }
        }
    }
}

// ---------------- residual VQ: one node per warp, 3 stages fused ------------
__global__ void k_vq(const float* __restrict__ h, const float* __restrict__ cbn,
                     float* __restrict__ ids, int l, float* __restrict__ loss) {
    __shared__ float bl;
    if (threadIdx.x == 0) bl = 0.f;
    __syncthreads();
    int node = blockIdx.x * 8 + (threadIdx.x >> 5);
    int lane = threadIdx.x & 31;
    float4 r = reinterpret_cast<const float4*>(h + (size_t)node * 128)[lane];
    float lsum = 0.f;
    for (int q = 0; q < G; q++) {
        const float* cb = cbn + q * C * 128;
        float best = -1e30f;
        int bi = 0;
        #pragma unroll 4
        for (int c = 0; c < C; c++) {
            float4 w = reinterpret_cast<const float4*>(cb + (size_t)c * 128)[lane];
            float p = r.x * w.x + r.y * w.y + r.z * w.z + r.w * w.w;
            #pragma unroll
            for (int o = 16; o > 0; o >>= 1) p += __shfl_xor_sync(0xffffffffu, p, o);
            if (p > best) { best = p; bi = c; }  // '>' keeps first index (matches argmax)
        }
        float4 w = reinterpret_cast<const float4*>(cb + (size_t)bi * 128)[lane];
        r.x -= w.x; r.y -= w.y; r.z -= w.z; r.w -= w.w;
        lsum += r.x * r.x + r.y * r.y + r.z * r.z + r.w * r.w;
        if (lane == 0) ids[(size_t)node * (L * G) + l * G + q] = (float)bi;
    }
    #pragma unroll
    for (int o = 16; o > 0; o >>= 1) lsum += __shfl_xor_sync(0xffffffffu, lsum, o);
    if (lane == 0) atomicAdd(&bl, lsum);
    __syncthreads();
    if (threadIdx.x == 0) atomicAdd(loss, bl);
}

__global__ void k_fin(const float* __restrict__ loss, float* __restrict__ dst) {
    *dst = (*loss) * (0.25f / ((float)N * (float)H));
}

// ---------------- host orchestration ----------------------------------------
extern "C" void kernel_launch(void* const* d_in, const int* in_sizes, int n_in,
                              void* d_out, int out_size) {
    const float* x        = (const float*)d_in[0];
    const int*   ei       = (const int*)d_in[1];
    const float* lin1_w   = (const float*)d_in[2];
    const float* lin1_b   = (const float*)d_in[3];
    const float* norms_g  = (const float*)d_in[4];
    const float* norms_b  = (const float*)d_in[5];
    const float* convl_w  = (const float*)d_in[6];
    const float* convl_b  = (const float*)d_in[7];
    const float* convr_w  = (const float*)d_in[8];
    const float* codebooks= (const float*)d_in[9];
    const float* fnorm_g  = (const float*)d_in[10];
    const float* fnorm_b  = (const float*)d_in[11];
    const float* lin2_w   = (const float*)d_in[12];
    const float* lin2_b   = (const float*)d_in[13];
    float* out = (float*)d_out;

    int *cnt, *row, *cur, *bsum, *csr;
    float *hA, *hB, *z, *agg, *cbn, *loss;
    cudaGetSymbolAddress((void**)&cnt,  g_cnt);
    cudaGetSymbolAddress((void**)&row,  g_row);
    cudaGetSymbolAddress((void**)&cur,  g_cur);
    cudaGetSymbolAddress((void**)&bsum, g_bsum);
    cudaGetSymbolAddress((void**)&csr,  g_csr);
    cudaGetSymbolAddress((void**)&hA,   g_hA);
    cudaGetSymbolAddress((void**)&hB,   g_hB);
    cudaGetSymbolAddress((void**)&z,    g_z);
    cudaGetSymbolAddress((void**)&agg,  g_agg);
    cudaGetSymbolAddress((void**)&cbn,  g_cbn);
    cudaGetSymbolAddress((void**)&loss, g_loss);

    // smem: As = 128*(BK+2)*8 = 34816 B; Ws = 32*(BN+4)*4
    constexpr int SMEM_H = 128 * 34 * 8 + 32 * 132 * 4;  // 51712 (BN=128)
    constexpr int SMEM_O = 128 * 34 * 8 + 32 * 68 * 4;   // 43520 (BN=64)
    cudaFuncSetAttribute(k_gemm2<128, false>, cudaFuncAttributeMaxDynamicSharedMemorySize, SMEM_H);
    cudaFuncSetAttribute(k_gemm2<128, true>,  cudaFuncAttributeMaxDynamicSharedMemorySize, SMEM_H);
    cudaFuncSetAttribute(k_gemm2<64, false>,  cudaFuncAttributeMaxDynamicSharedMemorySize, SMEM_O);

    const int NB = (N + 1023) / 1024;   // 98
    const int GB = (N + 127) / 128;     // 782 GEMM blocks

    k_zero<<<(N + 255) / 256, 256>>>(cnt, cur, loss);
    k_count<<<(E + 255) / 256, 256>>>(ei, cnt);
    k_scan_block<<<NB, 1024>>>(cnt, row, bsum);
    k_scan_sums<<<1, 128>>>(bsum, NB);
    k_scan_add<<<NB, 1024>>>(row, bsum);
    k_fill<<<(E + 255) / 256, 256>>>(ei, row, cur, csr);
    k_cbnorm<<<L * G * C, 32>>>(codebooks, cbn);

    k_gemm2<128, false><<<GB, 256, SMEM_H>>>(x, lin1_w, lin1_b, nullptr, nullptr, hA);

    float* hcur = hA;
    float* hnext = hB;
    for (int l = 0; l < L; l++) {
        k_ln<<<N, 128>>>(hcur, norms_g + (size_t)l * H, norms_b + (size_t)l * H, z);
        k_agg<<<N, 128>>>(z, csr, row, cnt, agg);
        k_gemm2<128, true><<<GB, 256, SMEM_H>>>(
            agg, convl_w + (size_t)l * H * H, convl_b + (size_t)l * H,
            z,   convr_w + (size_t)l * H * H, hnext);
        k_vq<<<N / 8, 256>>>(hnext, cbn + (size_t)l * G * C * H,
                             out + (size_t)N * OUTC + 1, l, loss);
        float* t = hcur; hcur = hnext; hnext = t;
    }

    k_ln<<<N, 128>>>(hcur, fnorm_g, fnorm_b, z);
    k_gemm2<64, false><<<GB, 256, SMEM_O>>>(z, lin2_w, lin2_b, nullptr, nullptr, out);
    k_fin<<<1, 1>>>(loss, out + (size_t)N * OUTC);
}

// round 7
// speedup vs baseline: 2.7753x; 1.1122x over previous
#include <cuda_runtime.h>
#include <math.h>

static constexpr int N   = 100000;
static constexpr int E   = 1600000;
static constexpr int H   = 128;
static constexpr int OUTC = 64;
static constexpr int L   = 3;
static constexpr int G   = 3;
static constexpr int C   = 16;

// ---------------- device scratch (static globals; no runtime allocation) ----
__device__ int   g_cnt[N];
__device__ int   g_row[N];
__device__ int   g_cur[N];
__device__ int   g_bsum[128];
__device__ int   g_csr[E];
__device__ float g_h[(size_t)N * H];     // pre-norm hidden (VQ input)
__device__ float g_zA[(size_t)N * H];    // normed activations (ping)
__device__ float g_zB[(size_t)N * H];    // normed activations (pong)
__device__ float g_cbn[L * G * C * H];
__device__ float g_loss;

// ---------------- packed f32x2 helpers ---------------------------------------
__device__ __forceinline__ unsigned long long fma2(unsigned long long a,
                                                   unsigned long long b,
                                                   unsigned long long c) {
    unsigned long long d;
    asm("fma.rn.f32x2 %0, %1, %2, %3;" : "=l"(d) : "l"(a), "l"(b), "l"(c));
    return d;
}
__device__ __forceinline__ unsigned long long packdup(float v) {
    unsigned long long p;
    asm("mov.b64 %0, {%1, %1};" : "=l"(p) : "f"(v));
    return p;
}

// ---------------- small utility kernels -------------------------------------
__global__ void k_zero(int* cnt, int* cur, float* loss) {
    int i = blockIdx.x * blockDim.x + threadIdx.x;
    if (i < N) { cnt[i] = 0; cur[i] = 0; }
    if (i == 0) *loss = 0.f;
}

__global__ void k_count(const int* __restrict__ ei, int* __restrict__ cnt) {
    int e = blockIdx.x * blockDim.x + threadIdx.x;
    if (e < E) atomicAdd(&cnt[ei[E + e]], 1);
}

__global__ void k_scan_block(const int* __restrict__ cnt, int* __restrict__ excl,
                             int* __restrict__ bsum) {
    __shared__ int s[1024];
    int i = blockIdx.x * 1024 + threadIdx.x;
    int v = (i < N) ? cnt[i] : 0;
    s[threadIdx.x] = v;
    __syncthreads();
    for (int off = 1; off < 1024; off <<= 1) {
        int t = (threadIdx.x >= off) ? s[threadIdx.x - off] : 0;
        __syncthreads();
        s[threadIdx.x] += t;
        __syncthreads();
    }
    if (i < N) excl[i] = s[threadIdx.x] - v;
    if (threadIdx.x == 1023) bsum[blockIdx.x] = s[1023];
}

__global__ void k_scan_sums(int* __restrict__ bsum, int nb) {
    __shared__ int s[128];
    int t = threadIdx.x;
    int v = (t < nb) ? bsum[t] : 0;
    s[t] = v;
    __syncthreads();
    for (int off = 1; off < 128; off <<= 1) {
        int u = (t >= off) ? s[t - off] : 0;
        __syncthreads();
        s[t] += u;
        __syncthreads();
    }
    if (t < nb) bsum[t] = s[t] - v;  // exclusive
}

__global__ void k_scan_add(int* __restrict__ excl, const int* __restrict__ bsum) {
    int i = blockIdx.x * 1024 + threadIdx.x;
    if (i < N) excl[i] += bsum[blockIdx.x];
}

__global__ void k_fill(const int* __restrict__ ei, const int* __restrict__ row,
                       int* __restrict__ cur, int* __restrict__ csr) {
    int e = blockIdx.x * blockDim.x + threadIdx.x;
    if (e < E) {
        int d = ei[E + e];
        int p = atomicAdd(&cur[d], 1);
        csr[row[d] + p] = ei[e];
    }
}

// normalize all codebook rows once: 144 rows of 128 floats, 1 warp per row
__global__ void k_cbnorm(const float* __restrict__ cb, float* __restrict__ cbn) {
    int id = blockIdx.x;
    int lane = threadIdx.x;
    float4 v = reinterpret_cast<const float4*>(cb + (size_t)id * 128)[lane];
    float sq = v.x * v.x + v.y * v.y + v.z * v.z + v.w * v.w;
    #pragma unroll
    for (int o = 16; o > 0; o >>= 1) sq += __shfl_xor_sync(0xffffffffu, sq, o);
    float inv = 1.f / (sqrtf(sq) + 1e-8f);
    v.x *= inv; v.y *= inv; v.z *= inv; v.w *= inv;
    reinterpret_cast<float4*>(cbn + (size_t)id * 128)[lane] = v;
}

// ---------------- fused FFMA2 GEMM -------------------------------------------
// Computes C[N,BN] = A @ W1^T + bias (+ gather-mean(Z) @ W1^T variant below).
// DUAL (conv layer): h = mean_agg(Z) @ W1^T + bias + Z @ W2^T, where the
// mean aggregation over CSR neighbors is performed inside the pass-0 A-loader.
// LNEPI: epilogue applies LayerNorm(+gamma,beta)+ReLU across the row (cols
// live in the 16 tx-lanes of a half-warp -> 4 xor-shuffles for mean/var),
// writing Zout; WRITE_H additionally writes the pre-norm h (VQ input).
// BM=128 rows/block, BK=32 k-chunk, 256 threads, thread (tx=tid%16,ty=tid/16)
// owns rows ty*8..+7 and col pairs {2tx+32c}.
template <int BN, bool DUAL, bool LNEPI, bool WRITE_H>
__global__ __launch_bounds__(256, 2)
void k_gemm2(const float* A1, const float* W1, const float* bias,
             const float* A2, const float* W2,
             const int* __restrict__ rowptr, const int* __restrict__ cnt,
             const int* __restrict__ csr,
             const float* lng, const float* lnb,
             float* Hout, float* Zout) {
    constexpr int BM = 128, BK = 32;
    constexpr int NP2 = BN / 32;       // col-pairs per thread (4 or 2)
    constexpr int ASTR = BK + 2;       // ull stride (even -> 16B-aligned ull2)
    constexpr int WSTR = BN + 4;       // float stride (even -> 8B-aligned ull)

    extern __shared__ char smraw[];
    unsigned long long* As = reinterpret_cast<unsigned long long*>(smraw); // [BM][ASTR]
    float* Ws = reinterpret_cast<float*>(As + BM * ASTR);                  // [BK][WSTR]

    const int tid = threadIdx.x;
    const int tx = tid & 15, ty = tid >> 4;
    const int row0 = blockIdx.x * BM;

    unsigned long long acc[8][NP2];
    #pragma unroll
    for (int r = 0; r < 8; r++)
        #pragma unroll
        for (int c = 0; c < NP2; c++) acc[r][c] = 0ull;

    #pragma unroll 1
    for (int pass = 0; pass < (DUAL ? 2 : 1); pass++) {
        const float* W = (DUAL && pass == 1) ? W2 : W1;
        #pragma unroll 1
        for (int kc = 0; kc < 128; kc += BK) {
            __syncthreads();
            if (DUAL && pass == 0) {
                // ---- gather mean over CSR neighbors of A2 (=z), cols kc..kc+31
                const int sub = tid & 7;          // float4 slot within 32 cols
                const int rloc = tid >> 3;        // 0..31
                #pragma unroll
                for (int p = 0; p < 4; p++) {
                    int r = rloc + p * 32;
                    int gr = row0 + r;
                    float ax = 0.f, ay = 0.f, az = 0.f, aw = 0.f;
                    if (gr < N) {
                        int st = rowptr[gr];
                        int dg = cnt[gr];
                        int i = 0;
                        for (; i + 2 <= dg; i += 2) {
                            int s0 = csr[st + i];
                            int s1 = csr[st + i + 1];
                            float4 v0 = *reinterpret_cast<const float4*>(
                                &A2[(size_t)s0 * 128 + kc + sub * 4]);
                            float4 v1 = *reinterpret_cast<const float4*>(
                                &A2[(size_t)s1 * 128 + kc + sub * 4]);
                            ax += v0.x; ay += v0.y; az += v0.z; aw += v0.w;
                            ax += v1.x; ay += v1.y; az += v1.z; aw += v1.w;
                        }
                        if (i < dg) {
                            int s0 = csr[st + i];
                            float4 v0 = *reinterpret_cast<const float4*>(
                                &A2[(size_t)s0 * 128 + kc + sub * 4]);
                            ax += v0.x; ay += v0.y; az += v0.z; aw += v0.w;
                        }
                        float inv = dg > 0 ? 1.f / (float)dg : 0.f;
                        ax *= inv; ay *= inv; az *= inv; aw *= inv;
                    }
                    unsigned long long* dst = &As[r * ASTR + sub * 4];
                    dst[0] = packdup(ax); dst[1] = packdup(ay);
                    dst[2] = packdup(az); dst[3] = packdup(aw);
                }
            } else {
                const float* A = DUAL ? A2 : A1;
                #pragma unroll
                for (int i = 0; i < 4; i++) {
                    int idx = tid + i * 256;
                    int r = idx >> 3;
                    int k4 = (idx & 7) * 4;
                    int gr = row0 + r;
                    float4 v = make_float4(0.f, 0.f, 0.f, 0.f);
                    if (gr < N)
                        v = *reinterpret_cast<const float4*>(&A[(size_t)gr * 128 + kc + k4]);
                    unsigned long long* dst = &As[r * ASTR + k4];
                    dst[0] = packdup(v.x); dst[1] = packdup(v.y);
                    dst[2] = packdup(v.z); dst[3] = packdup(v.w);
                }
            }
            // ---- load W chunk: BN x BK floats, transposed to [k][n] ----
            #pragma unroll
            for (int i = 0; i < BN / 32; i++) {
                int idx = tid + i * 256;
                int n = idx >> 3;
                int k4 = (idx & 7) * 4;
                float4 w = *reinterpret_cast<const float4*>(&W[(size_t)n * 128 + kc + k4]);
                Ws[(k4 + 0) * WSTR + n] = w.x;
                Ws[(k4 + 1) * WSTR + n] = w.y;
                Ws[(k4 + 2) * WSTR + n] = w.z;
                Ws[(k4 + 3) * WSTR + n] = w.w;
            }
            __syncthreads();
            // ---- compute ----
            #pragma unroll
            for (int k = 0; k < BK; k += 2) {
                longlong2 ap[8];
                #pragma unroll
                for (int r = 0; r < 8; r++)
                    ap[r] = *reinterpret_cast<const longlong2*>(&As[(ty * 8 + r) * ASTR + k]);
                unsigned long long wp0[NP2], wp1[NP2];
                const unsigned long long* wr0 =
                    reinterpret_cast<const unsigned long long*>(Ws + k * WSTR);
                const unsigned long long* wr1 =
                    reinterpret_cast<const unsigned long long*>(Ws + (k + 1) * WSTR);
                #pragma unroll
                for (int c = 0; c < NP2; c++) {
                    wp0[c] = wr0[tx + 16 * c];
                    wp1[c] = wr1[tx + 16 * c];
                }
                #pragma unroll
                for (int r = 0; r < 8; r++)
                    #pragma unroll
                    for (int c = 0; c < NP2; c++) {
                        acc[r][c] = fma2((unsigned long long)ap[r].x, wp0[c], acc[r][c]);
                        acc[r][c] = fma2((unsigned long long)ap[r].y, wp1[c], acc[r][c]);
                    }
            }
        }
    }

    // ---- epilogue ----
    float2 bv[NP2];
    #pragma unroll
    for (int c = 0; c < NP2; c++) {
        int col = 2 * tx + 32 * c;
        bv[c].x = bias[col];
        bv[c].y = bias[col + 1];
    }
    if (LNEPI) {
        float2 gv[NP2], btv[NP2];
        #pragma unroll
        for (int c = 0; c < NP2; c++) {
            int col = 2 * tx + 32 * c;
            gv[c].x = lng[col];  gv[c].y = lng[col + 1];
            btv[c].x = lnb[col]; btv[c].y = lnb[col + 1];
        }
        #pragma unroll
        for (int r = 0; r < 8; r++) {
            int gr = row0 + ty * 8 + r;
            float v[2 * NP2];
            float s = 0.f, q = 0.f;
            #pragma unroll
            for (int c = 0; c < NP2; c++) {
                float lo, hi;
                asm("mov.b64 {%0, %1}, %2;" : "=f"(lo), "=f"(hi) : "l"(acc[r][c]));
                lo += bv[c].x; hi += bv[c].y;
                v[2 * c] = lo; v[2 * c + 1] = hi;
                s += lo + hi;
                q += lo * lo + hi * hi;
            }
            #pragma unroll
            for (int o = 8; o > 0; o >>= 1) {
                s += __shfl_xor_sync(0xffffffffu, s, o);
                q += __shfl_xor_sync(0xffffffffu, q, o);
            }
            float m = s * (1.f / 128.f);
            float var = q * (1.f / 128.f) - m * m;
            float rs = rsqrtf(var + 1e-5f);
            if (gr < N) {
                #pragma unroll
                for (int c = 0; c < NP2; c++) {
                    int col = 2 * tx + 32 * c;
                    if (WRITE_H)
                        *reinterpret_cast<float2*>(&Hout[(size_t)gr * BN + col]) =
                            make_float2(v[2 * c], v[2 * c + 1]);
                    float z0 = fmaxf((v[2 * c]     - m) * rs * gv[c].x + btv[c].x, 0.f);
                    float z1 = fmaxf((v[2 * c + 1] - m) * rs * gv[c].y + btv[c].y, 0.f);
                    *reinterpret_cast<float2*>(&Zout[(size_t)gr * BN + col]) =
                        make_float2(z0, z1);
                }
            }
        }
    } else {
        #pragma unroll
        for (int r = 0; r < 8; r++) {
            int gr = row0 + ty * 8 + r;
            if (gr < N) {
                #pragma unroll
                for (int c = 0; c < NP2; c++) {
                    float lo, hi;
                    asm("mov.b64 {%0, %1}, %2;" : "=f"(lo), "=f"(hi) : "l"(acc[r][c]));
                    float2 o = make_float2(lo + bv[c].x, hi + bv[c].y);
                    *reinterpret_cast<float2*>(&Zout[(size_t)gr * BN + 2 * tx + 32 * c]) = o;
                }
            }
        }
    }
}

// ---------------- residual VQ: one node per warp, 3 stages fused ------------
__global__ void k_vq(const float* __restrict__ h, const float* __restrict__ cbn,
                     float* __restrict__ ids, int l, float* __restrict__ loss) {
    __shared__ float bl;
    if (threadIdx.x == 0) bl = 0.f;
    __syncthreads();
    int node = blockIdx.x * 8 + (threadIdx.x >> 5);
    int lane = threadIdx.x & 31;
    float4 r = reinterpret_cast<const float4*>(h + (size_t)node * 128)[lane];
    float lsum = 0.f;
    for (int q = 0; q < G; q++) {
        const float* cb = cbn + q * C * 128;
        float best = -1e30f;
        int bi = 0;
        #pragma unroll 4
        for (int c = 0; c < C; c++) {
            float4 w = reinterpret_cast<const float4*>(cb + (size_t)c * 128)[lane];
            float p = r.x * w.x + r.y * w.y + r.z * w.z + r.w * w.w;
            #pragma unroll
            for (int o = 16; o > 0; o >>= 1) p += __shfl_xor_sync(0xffffffffu, p, o);
            if (p > best) { best = p; bi = c; }  // '>' keeps first index (matches argmax)
        }
        float4 w = reinterpret_cast<const float4*>(cb + (size_t)bi * 128)[lane];
        r.x -= w.x; r.y -= w.y; r.z -= w.z; r.w -= w.w;
        lsum += r.x * r.x + r.y * r.y + r.z * r.z + r.w * r.w;
        if (lane == 0) ids[(size_t)node * (L * G) + l * G + q] = (float)bi;
    }
    #pragma unroll
    for (int o = 16; o > 0; o >>= 1) lsum += __shfl_xor_sync(0xffffffffu, lsum, o);
    if (lane == 0) atomicAdd(&bl, lsum);
    __syncthreads();
    if (threadIdx.x == 0) atomicAdd(loss, bl);
}

__global__ void k_fin(const float* __restrict__ loss, float* __restrict__ dst) {
    *dst = (*loss) * (0.25f / ((float)N * (float)H));
}

// ---------------- host orchestration ----------------------------------------
extern "C" void kernel_launch(void* const* d_in, const int* in_sizes, int n_in,
                              void* d_out, int out_size) {
    const float* x        = (const float*)d_in[0];
    const int*   ei       = (const int*)d_in[1];
    const float* lin1_w   = (const float*)d_in[2];
    const float* lin1_b   = (const float*)d_in[3];
    const float* norms_g  = (const float*)d_in[4];
    const float* norms_b  = (const float*)d_in[5];
    const float* convl_w  = (const float*)d_in[6];
    const float* convl_b  = (const float*)d_in[7];
    const float* convr_w  = (const float*)d_in[8];
    const float* codebooks= (const float*)d_in[9];
    const float* fnorm_g  = (const float*)d_in[10];
    const float* fnorm_b  = (const float*)d_in[11];
    const float* lin2_w   = (const float*)d_in[12];
    const float* lin2_b   = (const float*)d_in[13];
    float* out = (float*)d_out;

    int *cnt, *rowp, *cur, *bsum, *csr;
    float *h, *zA, *zB, *cbn, *loss;
    cudaGetSymbolAddress((void**)&cnt,  g_cnt);
    cudaGetSymbolAddress((void**)&rowp, g_row);
    cudaGetSymbolAddress((void**)&cur,  g_cur);
    cudaGetSymbolAddress((void**)&bsum, g_bsum);
    cudaGetSymbolAddress((void**)&csr,  g_csr);
    cudaGetSymbolAddress((void**)&h,    g_h);
    cudaGetSymbolAddress((void**)&zA,   g_zA);
    cudaGetSymbolAddress((void**)&zB,   g_zB);
    cudaGetSymbolAddress((void**)&cbn,  g_cbn);
    cudaGetSymbolAddress((void**)&loss, g_loss);

    // smem: As = 128*(BK+2)*8 = 34816 B; Ws = 32*(BN+4)*4
    constexpr int SMEM_H = 128 * 34 * 8 + 32 * 132 * 4;  // 51712 (BN=128)
    constexpr int SMEM_O = 128 * 34 * 8 + 32 * 68 * 4;   // 43520 (BN=64)
    cudaFuncSetAttribute((const void*)k_gemm2<128, false, true, false>,
                         cudaFuncAttributeMaxDynamicSharedMemorySize, SMEM_H);
    cudaFuncSetAttribute((const void*)k_gemm2<128, true, true, true>,
                         cudaFuncAttributeMaxDynamicSharedMemorySize, SMEM_H);
    cudaFuncSetAttribute((const void*)k_gemm2<64, false, false, false>,
                         cudaFuncAttributeMaxDynamicSharedMemorySize, SMEM_O);

    const int NB = (N + 1023) / 1024;   // 98
    const int GB = (N + 127) / 128;     // 782 GEMM blocks

    k_zero<<<(N + 255) / 256, 256>>>(cnt, cur, loss);
    k_count<<<(E + 255) / 256, 256>>>(ei, cnt);
    k_scan_block<<<NB, 1024>>>(cnt, rowp, bsum);
    k_scan_sums<<<1, 128>>>(bsum, NB);
    k_scan_add<<<NB, 1024>>>(rowp, bsum);
    k_fill<<<(E + 255) / 256, 256>>>(ei, rowp, cur, csr);
    k_cbnorm<<<L * G * C, 32>>>(codebooks, cbn);

    // lin1 + LayerNorm(norms0) + ReLU fused -> z0 (h0 never needed)
    k_gemm2<128, false, true, false><<<GB, 256, SMEM_H>>>(
        x, lin1_w, lin1_b, nullptr, nullptr,
        nullptr, nullptr, nullptr,
        norms_g, norms_b, nullptr, zA);

    float* zin = zA;
    float* zout = zB;
    for (int l = 0; l < L; l++) {
        const float* lg = (l < L - 1) ? norms_g + (size_t)(l + 1) * H : fnorm_g;
        const float* lb = (l < L - 1) ? norms_b + (size_t)(l + 1) * H : fnorm_b;
        // fused: gather-mean(zin) @ Wl^T + bias + zin @ Wr^T -> h;
        // LN(next norm)+ReLU -> zout
        k_gemm2<128, true, true, true><<<GB, 256, SMEM_H>>>(
            nullptr, convl_w + (size_t)l * H * H, convl_b + (size_t)l * H,
            zin, convr_w + (size_t)l * H * H,
            rowp, cnt, csr,
            lg, lb, h, zout);
        k_vq<<<N / 8, 256>>>(h, cbn + (size_t)l * G * C * H,
                             out + (size_t)N * OUTC + 1, l, loss);
        float* t = zin; zin = zout; zout = t;
    }

    // lin2 on final normed activations (zin after last swap)
    k_gemm2<64, false, false, false><<<GB, 256, SMEM_O>>>(
        zin, lin2_w, lin2_b, nullptr, nullptr,
        nullptr, nullptr, nullptr,
        nullptr, nullptr, nullptr, out);
    k_fin<<<1, 1>>>(loss, out + (size_t)N * OUTC);
}

// round 10
// speedup vs baseline: 2.9219x; 1.0528x over previous
#include <cuda_runtime.h>
#include <math.h>
#include <stdint.h>

static constexpr int N   = 100000;
static constexpr int E   = 1600000;
static constexpr int H   = 128;
static constexpr int OUTC = 64;
static constexpr int L   = 3;
static constexpr int G   = 3;
static constexpr int C   = 16;

// ---------------- device scratch (static globals; no runtime allocation) ----
__device__ int   g_cnt[N];
__device__ int   g_row[N];
__device__ int   g_cur[N];
__device__ int   g_bsum[128];
__device__ int   g_csr[E];
__device__ float g_h[(size_t)N * H];     // pre-norm hidden (VQ input)
__device__ float g_zA[(size_t)N * H];    // normed activations (ping)
__device__ float g_zB[(size_t)N * H];    // normed activations (pong)
__device__ float g_cbn[L * G * C * H];
__device__ float g_loss;

// ---------------- packed f32x2 / async-copy helpers --------------------------
__device__ __forceinline__ unsigned long long fma2(unsigned long long a,
                                                   unsigned long long b,
                                                   unsigned long long c) {
    unsigned long long d;
    asm("fma.rn.f32x2 %0, %1, %2, %3;" : "=l"(d) : "l"(a), "l"(b), "l"(c));
    return d;
}
__device__ __forceinline__ unsigned long long packdup(float v) {
    unsigned long long p;
    asm("mov.b64 %0, {%1, %1};" : "=l"(p) : "f"(v));
    return p;
}
__device__ __forceinline__ uint32_t s2u(const void* p) {
    uint32_t a;
    asm("{ .reg .u64 t; cvta.to.shared.u64 t, %1; cvt.u32.u64 %0, t; }"
        : "=r"(a) : "l"(p));
    return a;
}
__device__ __forceinline__ void cpa16(uint32_t dst, const void* src, int bytes) {
    asm volatile("cp.async.ca.shared.global [%0], [%1], 16, %2;"
                 :: "r"(dst), "l"(src), "r"(bytes));
}
__device__ __forceinline__ void cpcommit() {
    asm volatile("cp.async.commit_group;" ::: "memory");
}
__device__ __forceinline__ void cpwait0() {
    asm volatile("cp.async.wait_group 0;" ::: "memory");
}

// ---------------- small utility kernels -------------------------------------
__global__ void k_zero(int* cnt, int* cur, float* loss) {
    int i = blockIdx.x * blockDim.x + threadIdx.x;
    if (i < N) { cnt[i] = 0; cur[i] = 0; }
    if (i == 0) *loss = 0.f;
}

__global__ void k_count(const int* __restrict__ ei, int* __restrict__ cnt) {
    int e = blockIdx.x * blockDim.x + threadIdx.x;
    if (e < E) atomicAdd(&cnt[ei[E + e]], 1);
}

__global__ void k_scan_block(const int* __restrict__ cnt, int* __restrict__ excl,
                             int* __restrict__ bsum) {
    __shared__ int s[1024];
    int i = blockIdx.x * 1024 + threadIdx.x;
    int v = (i < N) ? cnt[i] : 0;
    s[threadIdx.x] = v;
    __syncthreads();
    for (int off = 1; off < 1024; off <<= 1) {
        int t = (threadIdx.x >= off) ? s[threadIdx.x - off] : 0;
        __syncthreads();
        s[threadIdx.x] += t;
        __syncthreads();
    }
    if (i < N) excl[i] = s[threadIdx.x] - v;
    if (threadIdx.x == 1023) bsum[blockIdx.x] = s[1023];
}

__global__ void k_scan_sums(int* __restrict__ bsum, int nb) {
    __shared__ int s[128];
    int t = threadIdx.x;
    int v = (t < nb) ? bsum[t] : 0;
    s[t] = v;
    __syncthreads();
    for (int off = 1; off < 128; off <<= 1) {
        int u = (t >= off) ? s[t - off] : 0;
        __syncthreads();
        s[t] += u;
        __syncthreads();
    }
    if (t < nb) bsum[t] = s[t] - v;  // exclusive
}

__global__ void k_scan_add(int* __restrict__ excl, const int* __restrict__ bsum) {
    int i = blockIdx.x * 1024 + threadIdx.x;
    if (i < N) excl[i] += bsum[blockIdx.x];
}

// fill CSR slots with EDGE IDS (atomic claim order is irrelevant; sorted later)
__global__ void k_fill(const int* __restrict__ ei, const int* __restrict__ row,
                       int* __restrict__ cur, int* __restrict__ csr) {
    int e = blockIdx.x * blockDim.x + threadIdx.x;
    if (e < E) {
        int d = ei[E + e];
        int p = atomicAdd(&cur[d], 1);
        csr[row[d] + p] = e;
    }
}

// Canonicalize: sort each row's edge-id segment ascending. Edge ids are unique,
// so this yields the exact EDGE ORDER -- the same order segment_sum accumulates
// in the reference. Deterministic across calls AND ULP-matched to the reference
// accumulation order (atomic fill order only approximated it).
__global__ void k_sort(const int* __restrict__ row, const int* __restrict__ cnt,
                       int* __restrict__ csr) {
    int n = blockIdx.x * blockDim.x + threadIdx.x;
    if (n >= N) return;
    int st = row[n], dg = cnt[n];
    for (int i = 1; i < dg; i++) {
        int v = csr[st + i];
        int j = i - 1;
        while (j >= 0 && csr[st + j] > v) {
            csr[st + j + 1] = csr[st + j];
            j--;
        }
        csr[st + j + 1] = v;
    }
}

// replace edge ids with source node ids (in place)
__global__ void k_map(const int* __restrict__ ei, int* __restrict__ csr) {
    int i = blockIdx.x * blockDim.x + threadIdx.x;
    if (i < E) csr[i] = ei[csr[i]];
}

// normalize all codebook rows once: 144 rows of 128 floats, 1 warp per row
__global__ void k_cbnorm(const float* __restrict__ cb, float* __restrict__ cbn) {
    int id = blockIdx.x;
    int lane = threadIdx.x;
    float4 v = reinterpret_cast<const float4*>(cb + (size_t)id * 128)[lane];
    float sq = v.x * v.x + v.y * v.y + v.z * v.z + v.w * v.w;
    #pragma unroll
    for (int o = 16; o > 0; o >>= 1) sq += __shfl_xor_sync(0xffffffffu, sq, o);
    float inv = 1.f / (sqrtf(sq) + 1e-8f);
    v.x *= inv; v.y *= inv; v.z *= inv; v.w *= inv;
    reinterpret_cast<float4*>(cbn + (size_t)id * 128)[lane] = v;
}

// ---------------- pipelined fused FFMA2 GEMM ---------------------------------
// C[N,BN] = A @ W1^T + bias  (DUAL: gather-mean(Z)@Wl^T + bias + Z@Wr^T).
// Software-pipelined with double-buffered smem: next chunk's A arrives via
// cp.async (plain) or register-gather+STS (CSR agg), next W prefetched into
// registers, both issued BEFORE computing the current chunk.
// Gather sums neighbors with strictly sequential scalar adds in edge order
// (matches the reference segment_sum accumulation order at the ULP level).
template <int BN, bool DUAL, bool LNEPI, bool WRITE_H>
__global__ __launch_bounds__(256, 2)
void k_gemm3(const float* A1, const float* W1, const float* bias,
             const float* A2, const float* W2,
             const int* __restrict__ rowptr, const int* __restrict__ cnt,
             const int* __restrict__ csr,
             const float* lng, const float* lnb,
             float* Hout, float* Zout) {
    constexpr int BM = 128, BK = 32;
    constexpr int NP2 = BN / 32;          // col-pairs per thread
    constexpr int ASTR = 36;              // float stride, 16B-aligned rows
    constexpr int WSTR = BN + 4;          // float stride (even -> ull ok)
    constexpr int NC = DUAL ? 8 : 4;      // chunks: [agg x4] + [z x4] | [A x4]
    constexpr int WREG = (BN * BK) / 1024;// float4 W regs per thread

    extern __shared__ float sm[];
    float* A0 = sm;
    float* A1s = sm + BM * ASTR;
    float* W0 = sm + 2 * BM * ASTR;
    float* W1s = W0 + BK * WSTR;
    const uint32_t a0u = s2u(A0), a1u = s2u(A1s);

    const int tid = threadIdx.x;
    const int tx = tid & 15, ty = tid >> 4;
    const int row0 = blockIdx.x * BM;

    unsigned long long acc[8][NP2];
    #pragma unroll
    for (int r = 0; r < 8; r++)
        #pragma unroll
        for (int c = 0; c < NP2; c++) acc[r][c] = 0ull;

    float4 wregs[WREG];

    // ---- issue A chunk c into buffer b (cp.async or gather+STS) ----
    auto issueA = [&](int c, int b) {
        if (DUAL && c < 4) {
            const int kc = c * 32;
            const int sub = tid & 7, rloc = tid >> 3;
            float* dst = b ? A1s : A0;
            #pragma unroll
            for (int p = 0; p < 4; p++) {
                int r = rloc + p * 32;
                int gr = row0 + r;
                float ax = 0.f, ay = 0.f, az = 0.f, aw = 0.f;
                if (gr < N) {
                    int st = rowptr[gr];
                    int dg = cnt[gr];
                    int i = 0;
                    for (; i + 2 <= dg; i += 2) {
                        int s0 = csr[st + i];
                        int s1 = csr[st + i + 1];
                        float4 v0 = *reinterpret_cast<const float4*>(
                            &A2[(size_t)s0 * 128 + kc + sub * 4]);
                        float4 v1 = *reinterpret_cast<const float4*>(
                            &A2[(size_t)s1 * 128 + kc + sub * 4]);
                        // strictly sequential adds (reference accumulation order)
                        ax += v0.x; ay += v0.y; az += v0.z; aw += v0.w;
                        ax += v1.x; ay += v1.y; az += v1.z; aw += v1.w;
                    }
                    if (i < dg) {
                        int s0 = csr[st + i];
                        float4 v0 = *reinterpret_cast<const float4*>(
                            &A2[(size_t)s0 * 128 + kc + sub * 4]);
                        ax += v0.x; ay += v0.y; az += v0.z; aw += v0.w;
                    }
                    float inv = dg > 0 ? 1.f / (float)dg : 0.f;
                    ax *= inv; ay *= inv; az *= inv; aw *= inv;
                }
                *reinterpret_cast<float4*>(&dst[r * ASTR + sub * 4]) =
                    make_float4(ax, ay, az, aw);
            }
        } else {
            const int kc = (DUAL ? (c - 4) : c) * 32;
            const float* A = DUAL ? A2 : A1;
            const uint32_t dst = b ? a1u : a0u;
            #pragma unroll
            for (int i = 0; i < 4; i++) {
                int idx = tid + i * 256;
                int r = idx >> 3;
                int k4 = (idx & 7) * 4;
                int gr = row0 + r;
                cpa16(dst + (uint32_t)(r * ASTR + k4) * 4,
                      &A[(size_t)gr * 128 + kc + k4], gr < N ? 16 : 0);
            }
        }
    };
    // ---- W chunk c: global -> regs ----
    auto ldgW = [&](int c) {
        const float* W = (DUAL && c >= 4) ? W2 : W1;
        const int kc = (DUAL ? (c & 3) : c) * 32;
        #pragma unroll
        for (int i = 0; i < WREG; i++) {
            int idx = tid + i * 256;
            int n = idx >> 3;
            int k4 = (idx & 7) * 4;
            wregs[i] = *reinterpret_cast<const float4*>(&W[(size_t)n * 128 + kc + k4]);
        }
    };
    // ---- W regs -> smem buffer b (transposed to [k][n]) ----
    auto stsW = [&](int b) {
        float* Wd = b ? W1s : W0;
        #pragma unroll
        for (int i = 0; i < WREG; i++) {
            int idx = tid + i * 256;
            int n = idx >> 3;
            int k4 = (idx & 7) * 4;
            Wd[(k4 + 0) * WSTR + n] = wregs[i].x;
            Wd[(k4 + 1) * WSTR + n] = wregs[i].y;
            Wd[(k4 + 2) * WSTR + n] = wregs[i].z;
            Wd[(k4 + 3) * WSTR + n] = wregs[i].w;
        }
    };

    // ---- prologue: chunk 0 ----
    issueA(0, 0);
    ldgW(0);
    stsW(0);
    cpcommit();

    int buf = 0;
    #pragma unroll 1
    for (int i = 0; i < NC; i++) {
        cpwait0();
        __syncthreads();
        if (i + 1 < NC) {
            issueA(i + 1, buf ^ 1);   // gather chunks also STS here (regs freed)
            ldgW(i + 1);
        }
        // ---- compute chunk i from buffer buf ----
        {
            const float* Ab = buf ? A1s : A0;
            const float* Wb = buf ? W1s : W0;
            #pragma unroll
            for (int k = 0; k < BK; k += 2) {
                unsigned long long wp0[NP2], wp1[NP2];
                const unsigned long long* wr0 =
                    reinterpret_cast<const unsigned long long*>(Wb + k * WSTR);
                const unsigned long long* wr1 =
                    reinterpret_cast<const unsigned long long*>(Wb + (k + 1) * WSTR);
                #pragma unroll
                for (int c = 0; c < NP2; c++) {
                    wp0[c] = wr0[tx + 16 * c];
                    wp1[c] = wr1[tx + 16 * c];
                }
                #pragma unroll
                for (int r = 0; r < 8; r++) {
                    float2 a = *reinterpret_cast<const float2*>(
                        &Ab[(ty * 8 + r) * ASTR + k]);
                    unsigned long long a0 = packdup(a.x);
                    unsigned long long a1 = packdup(a.y);
                    #pragma unroll
                    for (int c = 0; c < NP2; c++) {
                        acc[r][c] = fma2(a0, wp0[c], acc[r][c]);
                        acc[r][c] = fma2(a1, wp1[c], acc[r][c]);
                    }
                }
            }
        }
        if (i + 1 < NC) stsW(buf ^ 1);
        cpcommit();
        buf ^= 1;
    }

    // ---- epilogue ----
    float2 bv[NP2];
    #pragma unroll
    for (int c = 0; c < NP2; c++) {
        int col = 2 * tx + 32 * c;
        bv[c].x = bias[col];
        bv[c].y = bias[col + 1];
    }
    if (LNEPI) {
        float2 gv[NP2], btv[NP2];
        #pragma unroll
        for (int c = 0; c < NP2; c++) {
            int col = 2 * tx + 32 * c;
            gv[c].x = lng[col];  gv[c].y = lng[col + 1];
            btv[c].x = lnb[col]; btv[c].y = lnb[col + 1];
        }
        #pragma unroll
        for (int r = 0; r < 8; r++) {
            int gr = row0 + ty * 8 + r;
            float v[2 * NP2];
            float s = 0.f, q = 0.f;
            #pragma unroll
            for (int c = 0; c < NP2; c++) {
                float lo, hi;
                asm("mov.b64 {%0, %1}, %2;" : "=f"(lo), "=f"(hi) : "l"(acc[r][c]));
                lo += bv[c].x; hi += bv[c].y;
                v[2 * c] = lo; v[2 * c + 1] = hi;
                s += lo + hi;
                q += lo * lo + hi * hi;
            }
            #pragma unroll
            for (int o = 8; o > 0; o >>= 1) {
                s += __shfl_xor_sync(0xffffffffu, s, o);
                q += __shfl_xor_sync(0xffffffffu, q, o);
            }
            float m = s * (1.f / 128.f);
            float var = q * (1.f / 128.f) - m * m;
            float rs = rsqrtf(var + 1e-5f);
            if (gr < N) {
                #pragma unroll
                for (int c = 0; c < NP2; c++) {
                    int col = 2 * tx + 32 * c;
                    if (WRITE_H)
                        *reinterpret_cast<float2*>(&Hout[(size_t)gr * BN + col]) =
                            make_float2(v[2 * c], v[2 * c + 1]);
                    float z0 = fmaxf((v[2 * c]     - m) * rs * gv[c].x + btv[c].x, 0.f);
                    float z1 = fmaxf((v[2 * c + 1] - m) * rs * gv[c].y + btv[c].y, 0.f);
                    *reinterpret_cast<float2*>(&Zout[(size_t)gr * BN + col]) =
                        make_float2(z0, z1);
                }
            }
        }
    } else {
        #pragma unroll
        for (int r = 0; r < 8; r++) {
            int gr = row0 + ty * 8 + r;
            if (gr < N) {
                #pragma unroll
                for (int c = 0; c < NP2; c++) {
                    float lo, hi;
                    asm("mov.b64 {%0, %1}, %2;" : "=f"(lo), "=f"(hi) : "l"(acc[r][c]));
                    float2 o = make_float2(lo + bv[c].x, hi + bv[c].y);
                    *reinterpret_cast<float2*>(&Zout[(size_t)gr * BN + 2 * tx + 32 * c]) = o;
                }
            }
        }
    }
}

// ---------------- residual VQ: one node per warp, 3 stages fused ------------
__global__ void k_vq(const float* __restrict__ h, const float* __restrict__ cbn,
                     float* __restrict__ ids, int l, float* __restrict__ loss) {
    __shared__ float bl;
    if (threadIdx.x == 0) bl = 0.f;
    __syncthreads();
    int node = blockIdx.x * 8 + (threadIdx.x >> 5);
    int lane = threadIdx.x & 31;
    float4 r = reinterpret_cast<const float4*>(h + (size_t)node * 128)[lane];
    float lsum = 0.f;
    for (int q = 0; q < G; q++) {
        const float* cb = cbn + q * C * 128;
        float best = -1e30f;
        int bi = 0;
        #pragma unroll 4
        for (int c = 0; c < C; c++) {
            float4 w = reinterpret_cast<const float4*>(cb + (size_t)c * 128)[lane];
            float p = r.x * w.x + r.y * w.y + r.z * w.z + r.w * w.w;
            #pragma unroll
            for (int o = 16; o > 0; o >>= 1) p += __shfl_xor_sync(0xffffffffu, p, o);
            if (p > best) { best = p; bi = c; }  // '>' keeps first index (matches argmax)
        }
        float4 w = reinterpret_cast<const float4*>(cb + (size_t)bi * 128)[lane];
        r.x -= w.x; r.y -= w.y; r.z -= w.z; r.w -= w.w;
        lsum += r.x * r.x + r.y * r.y + r.z * r.z + r.w * r.w;
        if (lane == 0) ids[(size_t)node * (L * G) + l * G + q] = (float)bi;
    }
    #pragma unroll
    for (int o = 16; o > 0; o >>= 1) lsum += __shfl_xor_sync(0xffffffffu, lsum, o);
    if (lane == 0) atomicAdd(&bl, lsum);
    __syncthreads();
    if (threadIdx.x == 0) atomicAdd(loss, bl);
}

__global__ void k_fin(const float* __restrict__ loss, float* __restrict__ dst) {
    *dst = (*loss) * (0.25f / ((float)N * (float)H));
}

// ---------------- host orchestration ----------------------------------------
extern "C" void kernel_launch(void* const* d_in, const int* in_sizes, int n_in,
                              void* d_out, int out_size) {
    const float* x        = (const float*)d_in[0];
    const int*   ei       = (const int*)d_in[1];
    const float* lin1_w   = (const float*)d_in[2];
    const float* lin1_b   = (const float*)d_in[3];
    const float* norms_g  = (const float*)d_in[4];
    const float* norms_b  = (const float*)d_in[5];
    const float* convl_w  = (const float*)d_in[6];
    const float* convl_b  = (const float*)d_in[7];
    const float* convr_w  = (const float*)d_in[8];
    const float* codebooks= (const float*)d_in[9];
    const float* fnorm_g  = (const float*)d_in[10];
    const float* fnorm_b  = (const float*)d_in[11];
    const float* lin2_w   = (const float*)d_in[12];
    const float* lin2_b   = (const float*)d_in[13];
    float* out = (float*)d_out;

    int *cnt, *rowp, *cur, *bsum, *csr;
    float *h, *zA, *zB, *cbn, *loss;
    cudaGetSymbolAddress((void**)&cnt,  g_cnt);
    cudaGetSymbolAddress((void**)&rowp, g_row);
    cudaGetSymbolAddress((void**)&cur,  g_cur);
    cudaGetSymbolAddress((void**)&bsum, g_bsum);
    cudaGetSymbolAddress((void**)&csr,  g_csr);
    cudaGetSymbolAddress((void**)&h,    g_h);
    cudaGetSymbolAddress((void**)&zA,   g_zA);
    cudaGetSymbolAddress((void**)&zB,   g_zB);
    cudaGetSymbolAddress((void**)&cbn,  g_cbn);
    cudaGetSymbolAddress((void**)&loss, g_loss);

    // smem: double-buffered A (plain float) + double-buffered W (transposed)
    constexpr int SMEM_H = (2 * 128 * 36 + 2 * 32 * 132) * 4;  // 70656 (BN=128)
    constexpr int SMEM_O = (2 * 128 * 36 + 2 * 32 * 68) * 4;   // 54272 (BN=64)
    cudaFuncSetAttribute((const void*)k_gemm3<128, false, true, false>,
                         cudaFuncAttributeMaxDynamicSharedMemorySize, SMEM_H);
    cudaFuncSetAttribute((const void*)k_gemm3<128, true, true, true>,
                         cudaFuncAttributeMaxDynamicSharedMemorySize, SMEM_H);
    cudaFuncSetAttribute((const void*)k_gemm3<64, false, false, false>,
                         cudaFuncAttributeMaxDynamicSharedMemorySize, SMEM_O);

    const int NB = (N + 1023) / 1024;   // 98
    const int GB = (N + 127) / 128;     // 782 GEMM blocks

    k_zero<<<(N + 255) / 256, 256>>>(cnt, cur, loss);
    k_count<<<(E + 255) / 256, 256>>>(ei, cnt);
    k_scan_block<<<NB, 1024>>>(cnt, rowp, bsum);
    k_scan_sums<<<1, 128>>>(bsum, NB);
    k_scan_add<<<NB, 1024>>>(rowp, bsum);
    k_fill<<<(E + 255) / 256, 256>>>(ei, rowp, cur, csr);     // edge ids
    k_sort<<<(N + 255) / 256, 256>>>(rowp, cnt, csr);         // -> exact edge order
    k_map<<<(E + 255) / 256, 256>>>(ei, csr);                 // -> src node ids
    k_cbnorm<<<L * G * C, 32>>>(codebooks, cbn);

    // lin1 + LayerNorm(norms0) + ReLU fused -> z0 (h0 never needed)
    k_gemm3<128, false, true, false><<<GB, 256, SMEM_H>>>(
        x, lin1_w, lin1_b, nullptr, nullptr,
        nullptr, nullptr, nullptr,
        norms_g, norms_b, nullptr, zA);

    float* zin = zA;
    float* zout = zB;
    for (int l = 0; l < L; l++) {
        const float* lg = (l < L - 1) ? norms_g + (size_t)(l + 1) * H : fnorm_g;
        const float* lb = (l < L - 1) ? norms_b + (size_t)(l + 1) * H : fnorm_b;
        // fused: gather-mean(zin) @ Wl^T + bias + zin @ Wr^T -> h;
        // LN(next norm)+ReLU -> zout
        k_gemm3<128, true, true, true><<<GB, 256, SMEM_H>>>(
            nullptr, convl_w + (size_t)l * H * H, convl_b + (size_t)l * H,
            zin, convr_w + (size_t)l * H * H,
            rowp, cnt, csr,
            lg, lb, h, zout);
        k_vq<<<N / 8, 256>>>(h, cbn + (size_t)l * G * C * H,
                             out + (size_t)N * OUTC + 1, l, loss);
        float* t = zin; zin = zout; zout = t;
    }

    // lin2 on final normed activations (zin after last swap)
    k_gemm3<64, false, false, false><<<GB, 256, SMEM_O>>>(
        zin, lin2_w, lin2_b, nullptr, nullptr,
        nullptr, nullptr, nullptr,
        nullptr, nullptr, nullptr, out);
    k_fin<<<1, 1>>>(loss, out + (size_t)N * OUTC);
}

// round 11
// speedup vs baseline: 2.9520x; 1.0103x over previous
#include <cuda_runtime.h>
#include <math.h>
#include <stdint.h>

static constexpr int N   = 100000;
static constexpr int E   = 1600000;
static constexpr int H   = 128;
static constexpr int OUTC = 64;
static constexpr int L   = 3;
static constexpr int G   = 3;
static constexpr int C   = 16;

// ---------------- device scratch (static globals; no runtime allocation) ----
__device__ int   g_cnt[N];
__device__ int   g_row[N];
__device__ int   g_cur[N];
__device__ int   g_bsum[128];
__device__ int   g_csr[E];
__device__ float g_h[(size_t)L * N * H];  // per-layer pre-norm hidden (VQ input)
__device__ float g_zA[(size_t)N * H];     // normed activations (ping)
__device__ float g_zB[(size_t)N * H];     // normed activations (pong)
__device__ float g_cbn[L * G * C * H];
__device__ float g_loss;

// ---------------- packed f32x2 / async-copy helpers --------------------------
__device__ __forceinline__ unsigned long long fma2(unsigned long long a,
                                                   unsigned long long b,
                                                   unsigned long long c) {
    unsigned long long d;
    asm("fma.rn.f32x2 %0, %1, %2, %3;" : "=l"(d) : "l"(a), "l"(b), "l"(c));
    return d;
}
__device__ __forceinline__ unsigned long long packdup(float v) {
    unsigned long long p;
    asm("mov.b64 %0, {%1, %1};" : "=l"(p) : "f"(v));
    return p;
}
__device__ __forceinline__ uint32_t s2u(const void* p) {
    uint32_t a;
    asm("{ .reg .u64 t; cvta.to.shared.u64 t, %1; cvt.u32.u64 %0, t; }"
        : "=r"(a) : "l"(p));
    return a;
}
__device__ __forceinline__ void cpa16(uint32_t dst, const void* src, int bytes) {
    asm volatile("cp.async.ca.shared.global [%0], [%1], 16, %2;"
                 :: "r"(dst), "l"(src), "r"(bytes));
}
__device__ __forceinline__ void cpcommit() {
    asm volatile("cp.async.commit_group;" ::: "memory");
}
__device__ __forceinline__ void cpwait0() {
    asm volatile("cp.async.wait_group 0;" ::: "memory");
}

// ---------------- small utility kernels -------------------------------------
__global__ void k_zero(int* cnt, int* cur, float* loss) {
    int i = blockIdx.x * blockDim.x + threadIdx.x;
    if (i < N) { cnt[i] = 0; cur[i] = 0; }
    if (i == 0) *loss = 0.f;
}

__global__ void k_count(const int* __restrict__ ei, int* __restrict__ cnt) {
    int e = blockIdx.x * blockDim.x + threadIdx.x;
    if (e < E) atomicAdd(&cnt[ei[E + e]], 1);
}

__global__ void k_scan_block(const int* __restrict__ cnt, int* __restrict__ excl,
                             int* __restrict__ bsum) {
    __shared__ int s[1024];
    int i = blockIdx.x * 1024 + threadIdx.x;
    int v = (i < N) ? cnt[i] : 0;
    s[threadIdx.x] = v;
    __syncthreads();
    for (int off = 1; off < 1024; off <<= 1) {
        int t = (threadIdx.x >= off) ? s[threadIdx.x - off] : 0;
        __syncthreads();
        s[threadIdx.x] += t;
        __syncthreads();
    }
    if (i < N) excl[i] = s[threadIdx.x] - v;
    if (threadIdx.x == 1023) bsum[blockIdx.x] = s[1023];
}

__global__ void k_scan_sums(int* __restrict__ bsum, int nb) {
    __shared__ int s[128];
    int t = threadIdx.x;
    int v = (t < nb) ? bsum[t] : 0;
    s[t] = v;
    __syncthreads();
    for (int off = 1; off < 128; off <<= 1) {
        int u = (t >= off) ? s[t - off] : 0;
        __syncthreads();
        s[t] += u;
        __syncthreads();
    }
    if (t < nb) bsum[t] = s[t] - v;  // exclusive
}

__global__ void k_scan_add(int* __restrict__ excl, const int* __restrict__ bsum) {
    int i = blockIdx.x * 1024 + threadIdx.x;
    if (i < N) excl[i] += bsum[blockIdx.x];
}

// fill CSR slots with EDGE IDS (atomic claim order is irrelevant; sorted later)
__global__ void k_fill(const int* __restrict__ ei, const int* __restrict__ row,
                       int* __restrict__ cur, int* __restrict__ csr) {
    int e = blockIdx.x * blockDim.x + threadIdx.x;
    if (e < E) {
        int d = ei[E + e];
        int p = atomicAdd(&cur[d], 1);
        csr[row[d] + p] = e;
    }
}

// Canonicalize: sort each row's edge-id segment ascending -> exact EDGE ORDER,
// the order segment_sum accumulates in the reference. Deterministic + ULP-matched.
__global__ void k_sort(const int* __restrict__ row, const int* __restrict__ cnt,
                       int* __restrict__ csr) {
    int n = blockIdx.x * blockDim.x + threadIdx.x;
    if (n >= N) return;
    int st = row[n], dg = cnt[n];
    for (int i = 1; i < dg; i++) {
        int v = csr[st + i];
        int j = i - 1;
        while (j >= 0 && csr[st + j] > v) {
            csr[st + j + 1] = csr[st + j];
            j--;
        }
        csr[st + j + 1] = v;
    }
}

// replace edge ids with source node ids (in place)
__global__ void k_map(const int* __restrict__ ei, int* __restrict__ csr) {
    int i = blockIdx.x * blockDim.x + threadIdx.x;
    if (i < E) csr[i] = ei[csr[i]];
}

// normalize all codebook rows once: 144 rows of 128 floats, 1 warp per row
__global__ void k_cbnorm(const float* __restrict__ cb, float* __restrict__ cbn) {
    int id = blockIdx.x;
    int lane = threadIdx.x;
    float4 v = reinterpret_cast<const float4*>(cb + (size_t)id * 128)[lane];
    float sq = v.x * v.x + v.y * v.y + v.z * v.z + v.w * v.w;
    #pragma unroll
    for (int o = 16; o > 0; o >>= 1) sq += __shfl_xor_sync(0xffffffffu, sq, o);
    float inv = 1.f / (sqrtf(sq) + 1e-8f);
    v.x *= inv; v.y *= inv; v.z *= inv; v.w *= inv;
    reinterpret_cast<float4*>(cbn + (size_t)id * 128)[lane] = v;
}

// ---------------- pipelined fused FFMA2 GEMM ---------------------------------
// C[N,BN] = A @ W1^T + bias  (DUAL: gather-mean(Z)@Wl^T + bias + Z@Wr^T).
// Software-pipelined, double-buffered smem; gather sums neighbors with strictly
// sequential scalar adds in edge order (ULP-matches reference segment_sum).
template <int BN, bool DUAL, bool LNEPI, bool WRITE_H>
__global__ __launch_bounds__(256, 2)
void k_gemm3(const float* A1, const float* W1, const float* bias,
             const float* A2, const float* W2,
             const int* __restrict__ rowptr, const int* __restrict__ cnt,
             const int* __restrict__ csr,
             const float* lng, const float* lnb,
             float* Hout, float* Zout) {
    constexpr int BM = 128, BK = 32;
    constexpr int NP2 = BN / 32;          // col-pairs per thread
    constexpr int ASTR = 36;              // float stride, 16B-aligned rows
    constexpr int WSTR = BN + 4;          // float stride (even -> ull ok)
    constexpr int NC = DUAL ? 8 : 4;      // chunks: [agg x4] + [z x4] | [A x4]
    constexpr int WREG = (BN * BK) / 1024;// float4 W regs per thread

    extern __shared__ float sm[];
    float* A0 = sm;
    float* A1s = sm + BM * ASTR;
    float* W0 = sm + 2 * BM * ASTR;
    float* W1s = W0 + BK * WSTR;
    const uint32_t a0u = s2u(A0), a1u = s2u(A1s);

    const int tid = threadIdx.x;
    const int tx = tid & 15, ty = tid >> 4;
    const int row0 = blockIdx.x * BM;

    unsigned long long acc[8][NP2];
    #pragma unroll
    for (int r = 0; r < 8; r++)
        #pragma unroll
        for (int c = 0; c < NP2; c++) acc[r][c] = 0ull;

    float4 wregs[WREG];

    // ---- issue A chunk c into buffer b (cp.async or gather+STS) ----
    auto issueA = [&](int c, int b) {
        if (DUAL && c < 4) {
            const int kc = c * 32;
            const int sub = tid & 7, rloc = tid >> 3;
            float* dst = b ? A1s : A0;
            #pragma unroll
            for (int p = 0; p < 4; p++) {
                int r = rloc + p * 32;
                int gr = row0 + r;
                float ax = 0.f, ay = 0.f, az = 0.f, aw = 0.f;
                if (gr < N) {
                    int st = rowptr[gr];
                    int dg = cnt[gr];
                    int i = 0;
                    for (; i + 2 <= dg; i += 2) {
                        int s0 = csr[st + i];
                        int s1 = csr[st + i + 1];
                        float4 v0 = *reinterpret_cast<const float4*>(
                            &A2[(size_t)s0 * 128 + kc + sub * 4]);
                        float4 v1 = *reinterpret_cast<const float4*>(
                            &A2[(size_t)s1 * 128 + kc + sub * 4]);
                        // strictly sequential adds (reference accumulation order)
                        ax += v0.x; ay += v0.y; az += v0.z; aw += v0.w;
                        ax += v1.x; ay += v1.y; az += v1.z; aw += v1.w;
                    }
                    if (i < dg) {
                        int s0 = csr[st + i];
                        float4 v0 = *reinterpret_cast<const float4*>(
                            &A2[(size_t)s0 * 128 + kc + sub * 4]);
                        ax += v0.x; ay += v0.y; az += v0.z; aw += v0.w;
                    }
                    float inv = dg > 0 ? 1.f / (float)dg : 0.f;
                    ax *= inv; ay *= inv; az *= inv; aw *= inv;
                }
                *reinterpret_cast<float4*>(&dst[r * ASTR + sub * 4]) =
                    make_float4(ax, ay, az, aw);
            }
        } else {
            const int kc = (DUAL ? (c - 4) : c) * 32;
            const float* A = DUAL ? A2 : A1;
            const uint32_t dst = b ? a1u : a0u;
            #pragma unroll
            for (int i = 0; i < 4; i++) {
                int idx = tid + i * 256;
                int r = idx >> 3;
                int k4 = (idx & 7) * 4;
                int gr = row0 + r;
                cpa16(dst + (uint32_t)(r * ASTR + k4) * 4,
                      &A[(size_t)gr * 128 + kc + k4], gr < N ? 16 : 0);
            }
        }
    };
    // ---- W chunk c: global -> regs ----
    auto ldgW = [&](int c) {
        const float* W = (DUAL && c >= 4) ? W2 : W1;
        const int kc = (DUAL ? (c & 3) : c) * 32;
        #pragma unroll
        for (int i = 0; i < WREG; i++) {
            int idx = tid + i * 256;
            int n = idx >> 3;
            int k4 = (idx & 7) * 4;
            wregs[i] = *reinterpret_cast<const float4*>(&W[(size_t)n * 128 + kc + k4]);
        }
    };
    // ---- W regs -> smem buffer b (transposed to [k][n]) ----
    auto stsW = [&](int b) {
        float* Wd = b ? W1s : W0;
        #pragma unroll
        for (int i = 0; i < WREG; i++) {
            int idx = tid + i * 256;
            int n = idx >> 3;
            int k4 = (idx & 7) * 4;
            Wd[(k4 + 0) * WSTR + n] = wregs[i].x;
            Wd[(k4 + 1) * WSTR + n] = wregs[i].y;
            Wd[(k4 + 2) * WSTR + n] = wregs[i].z;
            Wd[(k4 + 3) * WSTR + n] = wregs[i].w;
        }
    };

    // ---- prologue: chunk 0 ----
    issueA(0, 0);
    ldgW(0);
    stsW(0);
    cpcommit();

    int buf = 0;
    #pragma unroll 1
    for (int i = 0; i < NC; i++) {
        cpwait0();
        __syncthreads();
        if (i + 1 < NC) {
            issueA(i + 1, buf ^ 1);   // gather chunks also STS here (regs freed)
            ldgW(i + 1);
        }
        // ---- compute chunk i from buffer buf ----
        {
            const float* Ab = buf ? A1s : A0;
            const float* Wb = buf ? W1s : W0;
            #pragma unroll
            for (int k = 0; k < BK; k += 2) {
                unsigned long long wp0[NP2], wp1[NP2];
                const unsigned long long* wr0 =
                    reinterpret_cast<const unsigned long long*>(Wb + k * WSTR);
                const unsigned long long* wr1 =
                    reinterpret_cast<const unsigned long long*>(Wb + (k + 1) * WSTR);
                #pragma unroll
                for (int c = 0; c < NP2; c++) {
                    wp0[c] = wr0[tx + 16 * c];
                    wp1[c] = wr1[tx + 16 * c];
                }
                #pragma unroll
                for (int r = 0; r < 8; r++) {
                    float2 a = *reinterpret_cast<const float2*>(
                        &Ab[(ty * 8 + r) * ASTR + k]);
                    unsigned long long a0 = packdup(a.x);
                    unsigned long long a1 = packdup(a.y);
                    #pragma unroll
                    for (int c = 0; c < NP2; c++) {
                        acc[r][c] = fma2(a0, wp0[c], acc[r][c]);
                        acc[r][c] = fma2(a1, wp1[c], acc[r][c]);
                    }
                }
            }
        }
        if (i + 1 < NC) stsW(buf ^ 1);
        cpcommit();
        buf ^= 1;
    }

    // ---- epilogue ----
    float2 bv[NP2];
    #pragma unroll
    for (int c = 0; c < NP2; c++) {
        int col = 2 * tx + 32 * c;
        bv[c].x = bias[col];
        bv[c].y = bias[col + 1];
    }
    if (LNEPI) {
        float2 gv[NP2], btv[NP2];
        #pragma unroll
        for (int c = 0; c < NP2; c++) {
            int col = 2 * tx + 32 * c;
            gv[c].x = lng[col];  gv[c].y = lng[col + 1];
            btv[c].x = lnb[col]; btv[c].y = lnb[col + 1];
        }
        #pragma unroll
        for (int r = 0; r < 8; r++) {
            int gr = row0 + ty * 8 + r;
            float v[2 * NP2];
            float s = 0.f, q = 0.f;
            #pragma unroll
            for (int c = 0; c < NP2; c++) {
                float lo, hi;
                asm("mov.b64 {%0, %1}, %2;" : "=f"(lo), "=f"(hi) : "l"(acc[r][c]));
                lo += bv[c].x; hi += bv[c].y;
                v[2 * c] = lo; v[2 * c + 1] = hi;
                s += lo + hi;
                q += lo * lo + hi * hi;
            }
            #pragma unroll
            for (int o = 8; o > 0; o >>= 1) {
                s += __shfl_xor_sync(0xffffffffu, s, o);
                q += __shfl_xor_sync(0xffffffffu, q, o);
            }
            float m = s * (1.f / 128.f);
            float var = q * (1.f / 128.f) - m * m;
            float rs = rsqrtf(var + 1e-5f);
            if (gr < N) {
                #pragma unroll
                for (int c = 0; c < NP2; c++) {
                    int col = 2 * tx + 32 * c;
                    if (WRITE_H)
                        *reinterpret_cast<float2*>(&Hout[(size_t)gr * BN + col]) =
                            make_float2(v[2 * c], v[2 * c + 1]);
                    float z0 = fmaxf((v[2 * c]     - m) * rs * gv[c].x + btv[c].x, 0.f);
                    float z1 = fmaxf((v[2 * c + 1] - m) * rs * gv[c].y + btv[c].y, 0.f);
                    *reinterpret_cast<float2*>(&Zout[(size_t)gr * BN + col]) =
                        make_float2(z0, z1);
                }
            }
        }
    } else {
        #pragma unroll
        for (int r = 0; r < 8; r++) {
            int gr = row0 + ty * 8 + r;
            if (gr < N) {
                #pragma unroll
                for (int c = 0; c < NP2; c++) {
                    float lo, hi;
                    asm("mov.b64 {%0, %1}, %2;" : "=f"(lo), "=f"(hi) : "l"(acc[r][c]));
                    float2 o = make_float2(lo + bv[c].x, hi + bv[c].y);
                    *reinterpret_cast<float2*>(&Zout[(size_t)gr * BN + 2 * tx + 32 * c]) = o;
                }
            }
        }
    }
}

// ---------------- residual VQ: one node per warp, 3 stages fused ------------
__global__ void k_vq(const float* __restrict__ h, const float* __restrict__ cbn,
                     float* __restrict__ ids, int l, float* __restrict__ loss) {
    __shared__ float bl;
    if (threadIdx.x == 0) bl = 0.f;
    __syncthreads();
    int node = blockIdx.x * 8 + (threadIdx.x >> 5);
    int lane = threadIdx.x & 31;
    float4 r = reinterpret_cast<const float4*>(h + (size_t)node * 128)[lane];
    float lsum = 0.f;
    for (int q = 0; q < G; q++) {
        const float* cb = cbn + q * C * 128;
        float best = -1e30f;
        int bi = 0;
        #pragma unroll 4
        for (int c = 0; c < C; c++) {
            float4 w = reinterpret_cast<const float4*>(cb + (size_t)c * 128)[lane];
            float p = r.x * w.x + r.y * w.y + r.z * w.z + r.w * w.w;
            #pragma unroll
            for (int o = 16; o > 0; o >>= 1) p += __shfl_xor_sync(0xffffffffu, p, o);
            if (p > best) { best = p; bi = c; }  // '>' keeps first index (matches argmax)
        }
        float4 w = reinterpret_cast<const float4*>(cb + (size_t)bi * 128)[lane];
        r.x -= w.x; r.y -= w.y; r.z -= w.z; r.w -= w.w;
        lsum += r.x * r.x + r.y * r.y + r.z * r.z + r.w * r.w;
        if (lane == 0) ids[(size_t)node * (L * G) + l * G + q] = (float)bi;
    }
    #pragma unroll
    for (int o = 16; o > 0; o >>= 1) lsum += __shfl_xor_sync(0xffffffffu, lsum, o);
    if (lane == 0) atomicAdd(&bl, lsum);
    __syncthreads();
    if (threadIdx.x == 0) atomicAdd(loss, bl);
}

__global__ void k_fin(const float* __restrict__ loss, float* __restrict__ dst) {
    *dst = (*loss) * (0.25f / ((float)N * (float)H));
}

// ---------------- host orchestration ----------------------------------------
extern "C" void kernel_launch(void* const* d_in, const int* in_sizes, int n_in,
                              void* d_out, int out_size) {
    const float* x        = (const float*)d_in[0];
    const int*   ei       = (const int*)d_in[1];
    const float* lin1_w   = (const float*)d_in[2];
    const float* lin1_b   = (const float*)d_in[3];
    const float* norms_g  = (const float*)d_in[4];
    const float* norms_b  = (const float*)d_in[5];
    const float* convl_w  = (const float*)d_in[6];
    const float* convl_b  = (const float*)d_in[7];
    const float* convr_w  = (const float*)d_in[8];
    const float* codebooks= (const float*)d_in[9];
    const float* fnorm_g  = (const float*)d_in[10];
    const float* fnorm_b  = (const float*)d_in[11];
    const float* lin2_w   = (const float*)d_in[12];
    const float* lin2_b   = (const float*)d_in[13];
    float* out = (float*)d_out;

    int *cnt, *rowp, *cur, *bsum, *csr;
    float *h, *zA, *zB, *cbn, *loss;
    cudaGetSymbolAddress((void**)&cnt,  g_cnt);
    cudaGetSymbolAddress((void**)&rowp, g_row);
    cudaGetSymbolAddress((void**)&cur,  g_cur);
    cudaGetSymbolAddress((void**)&bsum, g_bsum);
    cudaGetSymbolAddress((void**)&csr,  g_csr);
    cudaGetSymbolAddress((void**)&h,    g_h);
    cudaGetSymbolAddress((void**)&zA,   g_zA);
    cudaGetSymbolAddress((void**)&zB,   g_zB);
    cudaGetSymbolAddress((void**)&cbn,  g_cbn);
    cudaGetSymbolAddress((void**)&loss, g_loss);

    // side streams + fork/join events (created once; graph capture replays nodes)
    static cudaStream_t sCSR = nullptr, sVQ = nullptr;
    static cudaEvent_t evF = nullptr, evCSR, evH0, evH1, evH2, evVQ;
    if (sCSR == nullptr) {
        cudaStreamCreateWithFlags(&sCSR, cudaStreamNonBlocking);
        cudaStreamCreateWithFlags(&sVQ,  cudaStreamNonBlocking);
        cudaEventCreateWithFlags(&evF,   cudaEventDisableTiming);
        cudaEventCreateWithFlags(&evCSR, cudaEventDisableTiming);
        cudaEventCreateWithFlags(&evH0,  cudaEventDisableTiming);
        cudaEventCreateWithFlags(&evH1,  cudaEventDisableTiming);
        cudaEventCreateWithFlags(&evH2,  cudaEventDisableTiming);
        cudaEventCreateWithFlags(&evVQ,  cudaEventDisableTiming);
    }
    cudaEvent_t evH[3] = {evH0, evH1, evH2};

    // smem: double-buffered A (plain float) + double-buffered W (transposed)
    constexpr int SMEM_H = (2 * 128 * 36 + 2 * 32 * 132) * 4;  // 70656 (BN=128)
    constexpr int SMEM_O = (2 * 128 * 36 + 2 * 32 * 68) * 4;   // 54272 (BN=64)
    cudaFuncSetAttribute((const void*)k_gemm3<128, false, true, false>,
                         cudaFuncAttributeMaxDynamicSharedMemorySize, SMEM_H);
    cudaFuncSetAttribute((const void*)k_gemm3<128, true, true, true>,
                         cudaFuncAttributeMaxDynamicSharedMemorySize, SMEM_H);
    cudaFuncSetAttribute((const void*)k_gemm3<64, false, false, false>,
                         cudaFuncAttributeMaxDynamicSharedMemorySize, SMEM_O);

    const int NB = (N + 1023) / 1024;   // 98
    const int GB = (N + 127) / 128;     // 782 GEMM blocks
    const size_t NH = (size_t)N * H;

    // ---- fork: CSR build chain runs concurrently with cbnorm + lin1 ----
    cudaEventRecord(evF, 0);
    cudaStreamWaitEvent(sCSR, evF, 0);
    k_zero<<<(N + 255) / 256, 256, 0, sCSR>>>(cnt, cur, loss);
    k_count<<<(E + 255) / 256, 256, 0, sCSR>>>(ei, cnt);
    k_scan_block<<<NB, 1024, 0, sCSR>>>(cnt, rowp, bsum);
    k_scan_sums<<<1, 128, 0, sCSR>>>(bsum, NB);
    k_scan_add<<<NB, 1024, 0, sCSR>>>(rowp, bsum);
    k_fill<<<(E + 255) / 256, 256, 0, sCSR>>>(ei, rowp, cur, csr);  // edge ids
    k_sort<<<(N + 255) / 256, 256, 0, sCSR>>>(rowp, cnt, csr);      // exact edge order
    k_map<<<(E + 255) / 256, 256, 0, sCSR>>>(ei, csr);              // src node ids
    cudaEventRecord(evCSR, sCSR);

    // ---- main stream: codebook norm + lin1 (+LN0+ReLU) -> z0 ----
    k_cbnorm<<<L * G * C, 32>>>(codebooks, cbn);
    k_gemm3<128, false, true, false><<<GB, 256, SMEM_H>>>(
        x, lin1_w, lin1_b, nullptr, nullptr,
        nullptr, nullptr, nullptr,
        norms_g, norms_b, nullptr, zA);

    // join: conv layers need the CSR
    cudaStreamWaitEvent(0, evCSR, 0);

    float* zin = zA;
    float* zout = zB;
    for (int l = 0; l < L; l++) {
        const float* lg = (l < L - 1) ? norms_g + (size_t)(l + 1) * H : fnorm_g;
        const float* lb = (l < L - 1) ? norms_b + (size_t)(l + 1) * H : fnorm_b;
        float* hl = h + (size_t)l * NH;   // per-layer slab: VQ reads while next GEMM runs
        k_gemm3<128, true, true, true><<<GB, 256, SMEM_H>>>(
            nullptr, convl_w + (size_t)l * H * H, convl_b + (size_t)l * H,
            zin, convr_w + (size_t)l * H * H,
            rowp, cnt, csr,
            lg, lb, hl, zout);
        // VQ on side stream, overlapping the next layer's GEMM / lin2
        cudaEventRecord(evH[l], 0);
        cudaStreamWaitEvent(sVQ, evH[l], 0);
        k_vq<<<N / 8, 256, 0, sVQ>>>(hl, cbn + (size_t)l * G * C * H,
                                     out + (size_t)N * OUTC + 1, l, loss);
        float* t = zin; zin = zout; zout = t;
    }

    // lin2 on final normed activations (independent of VQ stream)
    k_gemm3<64, false, false, false><<<GB, 256, SMEM_O>>>(
        zin, lin2_w, lin2_b, nullptr, nullptr,
        nullptr, nullptr, nullptr,
        nullptr, nullptr, nullptr, out);

    // join VQ stream, then finalize loss
    cudaEventRecord(evVQ, sVQ);
    cudaStreamWaitEvent(0, evVQ, 0);
    k_fin<<<1, 1>>>(loss, out + (size_t)N * OUTC);
}